// round 12
// baseline (speedup 1.0000x reference)
#include <cuda_runtime.h>
#include <cuda_bf16.h>
#include <cuda_fp16.h>
#include <cstdint>

#define MAXN 100000
#define MAXE 1600000
#define MAXT (MAXE + MAXN)

// ---------------- scratch (static device globals; no runtime allocation) ----------------
__device__ __align__(16) __half g_h16[(size_t)MAXN * 128]; // per-layer h = x @ W (fp16)
__device__ __align__(16) float g_x[(size_t)MAXN * 128];    // activations between layers
__device__ float g_as[MAXN];
__device__ float g_ad[MAXN];
__device__ int   g_deg[MAXN];
__device__ int   g_off[MAXN + 1];
__device__ int   g_cur[MAXN];
__device__ int   g_srcs[MAXT];
__device__ int   g_is64;
__device__ int   g_bsum[512];
__device__ __align__(8) __nv_bfloat16 g_B1h[128 * 512], g_B1l[128 * 512];
__device__ __align__(8) __nv_bfloat16 g_B2h[128 * 128], g_B2l[128 * 128];
__device__ __align__(8) __nv_bfloat16 g_B3h[64 * 128],  g_B3l[64 * 128];

// ================= helpers =================
__device__ __forceinline__ uint32_t smem_u32(const void* p) {
    uint32_t a;
    asm("{ .reg .u64 t; cvta.to.shared.u64 t, %1; cvt.u32.u64 %0, t; }" : "=r"(a) : "l"(p));
    return a;
}
__device__ __forceinline__ uint32_t pack_bf16(float a, float b) {
    uint32_t r;
    asm("cvt.rn.bf16x2.f32 %0, %1, %2;" : "=r"(r) : "f"(b), "f"(a));
    return r;
}
__device__ __forceinline__ float bf16_round(float x) {
    return __bfloat162float(__float2bfloat16(x));
}
__device__ __forceinline__ void ldm_x4(uint32_t* r, uint32_t addr) {
    asm volatile("ldmatrix.sync.aligned.m8n8.x4.shared.b16 {%0,%1,%2,%3}, [%4];"
                 : "=r"(r[0]), "=r"(r[1]), "=r"(r[2]), "=r"(r[3]) : "r"(addr));
}
__device__ __forceinline__ void mma_bf16(float* c, const uint32_t* a, const uint32_t* b) {
    asm volatile(
        "mma.sync.aligned.m16n8k16.row.col.f32.bf16.bf16.f32 "
        "{%0,%1,%2,%3},{%4,%5,%6,%7},{%8,%9},{%0,%1,%2,%3};"
        : "+f"(c[0]), "+f"(c[1]), "+f"(c[2]), "+f"(c[3])
        : "r"(a[0]), "r"(a[1]), "r"(a[2]), "r"(a[3]), "r"(b[0]), "r"(b[1]));
}
__device__ __forceinline__ void sts64(uint32_t addr, uint32_t a, uint32_t b) {
    asm volatile("st.shared.v2.u32 [%0], {%1, %2};" :: "r"(addr), "r"(a), "r"(b) : "memory");
}
__device__ __forceinline__ void cp_async8(uint32_t saddr, const void* gptr) {
    asm volatile("cp.async.ca.shared.global [%0], [%1], 8;"
                 :: "r"(saddr), "l"(gptr) : "memory");
}
__device__ __forceinline__ void cp_async_commit_wait() {
    asm volatile("cp.async.commit_group;" ::: "memory");
    asm volatile("cp.async.wait_group 0;" ::: "memory");
}
__device__ __forceinline__ float leaky02(float v) { return v > 0.f ? v : 0.2f * v; }

// ---------------- adjacency dtype detection ----------------
__global__ void detect_kernel(const int* __restrict__ w) {
    if (threadIdx.x == 0) {
        int all0 = 1;
        #pragma unroll 1
        for (int i = 0; i < 64; i++)
            if (w[2 * i + 1] != 0) { all0 = 0; break; }
        g_is64 = all0;
    }
}

// ---------------- CSR build ----------------
__global__ void init_deg_kernel(int n) {
    int i = blockIdx.x * blockDim.x + threadIdx.x;
    if (i < n) g_deg[i] = 1;  // self-loop
}

__global__ void count2_kernel(const int* __restrict__ dst32,
                              const int* __restrict__ dst64, int e) {
    int i = blockIdx.x * blockDim.x + threadIdx.x;
    if (i >= e) return;
    int is64 = g_is64;
    int d = is64 ? dst64[2 * i] : dst32[i];
    atomicAdd(&g_deg[d], 1);
}

#define SCAN_BS 512
__global__ void blockscan_kernel(int n) {
    __shared__ int sh[SCAN_BS];
    int t = threadIdx.x;
    int i = blockIdx.x * SCAN_BS + t;
    int v = (i < n) ? g_deg[i] : 0;
    sh[t] = v;
    __syncthreads();
    #pragma unroll
    for (int d = 1; d < SCAN_BS; d <<= 1) {
        int x = (t >= d) ? sh[t - d] : 0;
        __syncthreads();
        sh[t] += x;
        __syncthreads();
    }
    if (i < n) g_off[i] = sh[t] - v;
    if (t == SCAN_BS - 1) g_bsum[blockIdx.x] = sh[t];
}

__global__ void bsumscan_kernel(int nb, int n) {
    __shared__ int sh[512];
    int t = threadIdx.x;
    int v = (t < nb) ? g_bsum[t] : 0;
    sh[t] = v;
    __syncthreads();
    #pragma unroll
    for (int d = 1; d < 512; d <<= 1) {
        int x = (t >= d) ? sh[t - d] : 0;
        __syncthreads();
        sh[t] += x;
        __syncthreads();
    }
    if (t < nb) g_bsum[t] = sh[t] - v;
    if (t == 511) g_off[n] = sh[511];
}

__global__ void addoff_kernel(int n) {
    int i = blockIdx.x * blockDim.x + threadIdx.x;
    if (i < n) {
        int o = g_off[i] + g_bsum[i >> 9];
        g_off[i] = o;
        g_cur[i] = o;
    }
}

__global__ void scatter2_kernel(const int* __restrict__ src,
                                const int* __restrict__ dst32,
                                const int* __restrict__ dst64, int e, int n) {
    int i = blockIdx.x * blockDim.x + threadIdx.x;
    int is64 = g_is64;
    if (i < e) {
        int d = is64 ? dst64[2 * i] : dst32[i];
        int s = is64 ? src[2 * i] : src[i];
        int p = atomicAdd(&g_cur[d], 1);
        g_srcs[p] = s;
    } else if (i < e + n) {
        int v = i - e;
        int p = atomicAdd(&g_cur[v], 1);
        g_srcs[p] = v;
    }
}

// ---------------- W transpose + bf16 hi/lo split ----------------
__global__ void wsplit_kernel(const float* __restrict__ W,
                              __nv_bfloat16* __restrict__ Bh,
                              __nv_bfloat16* __restrict__ Bl, int K, int Nd) {
    int i = blockIdx.x * blockDim.x + threadIdx.x;
    if (i >= K * Nd) return;
    int k = i / Nd, nn = i % Nd;
    float x = W[i];
    float h = bf16_round(x);
    Bh[(size_t)nn * K + k] = __float2bfloat16(h);
    Bl[(size_t)nn * K + k] = __float2bfloat16(x - h);
}

// ---------------- mma.sync bf16-split GEMM + fused alpha dots ----------------
// NDIM=128: warp grid 4(M)x2(N), warp tile 32x64. Vector STS + cp.async B staging.
template <int NDIM>
__global__ void __launch_bounds__(256, 2)
mma_gemm_kernel(const float* __restrict__ Ain, int useGX, int M, int K,
                const __nv_bfloat16* __restrict__ Bhi,
                const __nv_bfloat16* __restrict__ Blo,
                const float* __restrict__ a_src, const float* __restrict__ a_dst) {
    constexpr int ABYTES = 128 * 128;
    constexpr int BBYTES = NDIM * 128;
    constexpr int BP = NDIM / 16;
    constexpr int MT = (NDIM == 128) ? 2 : 1;
    constexpr int MROWS = MT * 16;
    extern __shared__ char smraw[];
    char* smem = (char*)(((uintptr_t)smraw + 1023) & ~(uintptr_t)1023);
    uint32_t aHiB = smem_u32(smem);
    uint32_t aLoB = aHiB + ABYTES;
    uint32_t bHiB = aHiB + 2 * ABYTES;
    uint32_t bLoB = bHiB + BBYTES;

    const float* A = useGX ? g_x : Ain;
    const int tid = threadIdx.x, wid = tid >> 5, lane = tid & 31;
    const int rowBase = blockIdx.x * 128;
    const int wm = (NDIM == 128) ? (wid & 3) : wid;
    const int wn = (NDIM == 128) ? (wid >> 2) : 0;

    float acc[MT][8][4];
    #pragma unroll
    for (int mt = 0; mt < MT; mt++)
        #pragma unroll
        for (int nt = 0; nt < 8; nt++)
            #pragma unroll
            for (int q = 0; q < 4; q++) acc[mt][nt][q] = 0.f;

    const int aRow = wm * MROWS + (lane & 7) + ((lane >> 3) & 1) * 8;
    const uint32_t aRowOff = (uint32_t)aRow * 128;
    const uint32_t aSwz = (uint32_t)(lane & 7) << 4;
    const uint32_t aHalf = ((lane >> 4) & 1) * 16;
    const uint32_t bRow4 = (uint32_t)((lane & 7) | ((lane >> 4) << 3));
    const uint32_t bRowOff4 = (uint32_t)(wn * 64 + bRow4) * 128;
    const uint32_t bSwz4 = (uint32_t)(lane & 7) << 4;
    const uint32_t bHalf4 = ((lane >> 3) & 1) * 16;

    const int sr = tid >> 4;
    const int cg = (tid & 15) * 4;
    const uint32_t stCol = (uint32_t)(cg * 2);

    const int nChunks = K >> 6;

    float4 pref[8];
    #pragma unroll
    for (int p = 0; p < 8; p++) {
        int gr = rowBase + p * 16 + sr;
        pref[p] = make_float4(0.f, 0.f, 0.f, 0.f);
        if (gr < M)
            pref[p] = *reinterpret_cast<const float4*>(&A[(size_t)gr * K + cg]);
    }

    for (int c = 0; c < nChunks; c++) {
        const int k0 = c << 6;
        // ---- B staging via cp.async (no register round-trip) ----
        #pragma unroll
        for (int p = 0; p < BP; p++) {
            int r = p * 16 + sr;
            uint32_t off = (uint32_t)r * 128 + (stCol ^ ((uint32_t)(r & 7) << 4));
            cp_async8(bHiB + off, &Bhi[(size_t)r * K + k0 + cg]);
            cp_async8(bLoB + off, &Blo[(size_t)r * K + k0 + cg]);
        }
        // ---- stage A from register prefetch (8B vector STS) ----
        #pragma unroll
        for (int p = 0; p < 8; p++) {
            int r = p * 16 + sr;
            float4 v = pref[p];
            float h0 = bf16_round(v.x), h1 = bf16_round(v.y);
            float h2 = bf16_round(v.z), h3 = bf16_round(v.w);
            uint32_t off = (uint32_t)r * 128 + (stCol ^ ((uint32_t)(r & 7) << 4));
            sts64(aHiB + off, pack_bf16(v.x, v.y), pack_bf16(v.z, v.w));
            sts64(aLoB + off, pack_bf16(v.x - h0, v.y - h1), pack_bf16(v.z - h2, v.w - h3));
        }
        cp_async_commit_wait();
        __syncthreads();

        // ---- prefetch A chunk c+1 (overlaps with MMA) ----
        if (c + 1 < nChunks) {
            const int k1 = (c + 1) << 6;
            #pragma unroll
            for (int p = 0; p < 8; p++) {
                int gr = rowBase + p * 16 + sr;
                pref[p] = make_float4(0.f, 0.f, 0.f, 0.f);
                if (gr < M)
                    pref[p] = *reinterpret_cast<const float4*>(&A[(size_t)gr * K + k1 + cg]);
            }
        }

        // ---- compute ----
        #pragma unroll
        for (int kt = 0; kt < 4; kt++) {
            uint32_t kc = (uint32_t)kt * 32;
            uint32_t aoff = aRowOff + ((kc + aHalf) ^ aSwz);
            uint32_t ahi[MT][4], alo[MT][4];
            #pragma unroll
            for (int mt = 0; mt < MT; mt++) {
                ldm_x4(ahi[mt], aHiB + aoff + (uint32_t)mt * 2048);
                ldm_x4(alo[mt], aLoB + aoff + (uint32_t)mt * 2048);
            }
            uint32_t bcol = (kc + bHalf4) ^ bSwz4;
            #pragma unroll
            for (int np = 0; np < 4; np++) {
                uint32_t boff = bRowOff4 + (uint32_t)np * 2048 + bcol;
                uint32_t bhi[4], blo[4];
                ldm_x4(bhi, bHiB + boff);
                ldm_x4(blo, bLoB + boff);
                #pragma unroll
                for (int mt = 0; mt < MT; mt++) {
                    mma_bf16(acc[mt][2 * np],     ahi[mt], &bhi[0]);
                    mma_bf16(acc[mt][2 * np],     ahi[mt], &blo[0]);
                    mma_bf16(acc[mt][2 * np],     alo[mt], &bhi[0]);
                    mma_bf16(acc[mt][2 * np + 1], ahi[mt], &bhi[2]);
                    mma_bf16(acc[mt][2 * np + 1], ahi[mt], &blo[2]);
                    mma_bf16(acc[mt][2 * np + 1], alo[mt], &bhi[2]);
                }
            }
        }
        __syncthreads();
    }

    // ---- epilogue: write h (fp16) + alpha dot partials ----
    int r0 = rowBase + wm * MROWS + (lane >> 2);
    int colb = (lane & 3) * 2;
    float sp[MT][2], dp[MT][2];
    #pragma unroll
    for (int mt = 0; mt < MT; mt++) { sp[mt][0] = sp[mt][1] = dp[mt][0] = dp[mt][1] = 0.f; }

    #pragma unroll
    for (int mt = 0; mt < MT; mt++) {
        int rA = r0 + mt * 16;
        #pragma unroll
        for (int nt = 0; nt < 8; nt++) {
            int col = wn * 64 + nt * 8 + colb;
            float a0 = a_src[col], a1 = a_src[col + 1];
            float e0 = a_dst[col], e1 = a_dst[col + 1];
            sp[mt][0] = fmaf(acc[mt][nt][0], a0, fmaf(acc[mt][nt][1], a1, sp[mt][0]));
            dp[mt][0] = fmaf(acc[mt][nt][0], e0, fmaf(acc[mt][nt][1], e1, dp[mt][0]));
            sp[mt][1] = fmaf(acc[mt][nt][2], a0, fmaf(acc[mt][nt][3], a1, sp[mt][1]));
            dp[mt][1] = fmaf(acc[mt][nt][2], e0, fmaf(acc[mt][nt][3], e1, dp[mt][1]));
            if (rA < M)
                *reinterpret_cast<__half2*>(&g_h16[(size_t)rA * NDIM + col]) =
                    __floats2half2_rn(acc[mt][nt][0], acc[mt][nt][1]);
            if (rA + 8 < M)
                *reinterpret_cast<__half2*>(&g_h16[(size_t)(rA + 8) * NDIM + col]) =
                    __floats2half2_rn(acc[mt][nt][2], acc[mt][nt][3]);
        }
    }
    #pragma unroll
    for (int o = 1; o <= 2; o <<= 1) {
        #pragma unroll
        for (int mt = 0; mt < MT; mt++) {
            sp[mt][0] += __shfl_xor_sync(0xffffffffu, sp[mt][0], o);
            dp[mt][0] += __shfl_xor_sync(0xffffffffu, dp[mt][0], o);
            sp[mt][1] += __shfl_xor_sync(0xffffffffu, sp[mt][1], o);
            dp[mt][1] += __shfl_xor_sync(0xffffffffu, dp[mt][1], o);
        }
    }

    if constexpr (NDIM == 128) {
        float* sal = (float*)smem;   // reuse A region: [128][4] s0,d0,s1,d1
        if ((lane & 3) == 0) {
            int lr = wm * MROWS + (lane >> 2);
            #pragma unroll
            for (int mt = 0; mt < MT; mt++) {
                #pragma unroll
                for (int rh = 0; rh < 2; rh++) {
                    int row = lr + mt * 16 + rh * 8;
                    sal[row * 4 + wn * 2]     = (rh == 0) ? sp[mt][0] : sp[mt][1];
                    sal[row * 4 + wn * 2 + 1] = (rh == 0) ? dp[mt][0] : dp[mt][1];
                }
            }
        }
        __syncthreads();
        if (tid < 128) {
            int gr = rowBase + tid;
            if (gr < M) {
                g_as[gr] = sal[tid * 4] + sal[tid * 4 + 2];
                g_ad[gr] = sal[tid * 4 + 1] + sal[tid * 4 + 3];
            }
        }
    } else {
        if ((lane & 3) == 0) {
            if (r0 < M)     { g_as[r0] = sp[0][0];     g_ad[r0] = dp[0][0]; }
            if (r0 + 8 < M) { g_as[r0 + 8] = sp[0][1]; g_ad[r0 + 8] = dp[0][1]; }
        }
    }
}

// ---------------- segment softmax + aggregation, fp16 h gather, MLP=8 ----------------
template <int DO, bool TO_GX>
__global__ void aggregate_kernel(const float* __restrict__ bias,
                                 float* __restrict__ outp, int n) {
    constexpr int VEC = DO / 32;
    int node = (blockIdx.x * blockDim.x + threadIdx.x) >> 5;
    int lane = threadIdx.x & 31;
    if (node >= n) return;
    int s0 = g_off[node], s1 = g_off[node + 1];
    float adn = g_ad[node];

    float acc[VEC];
    #pragma unroll
    for (int k = 0; k < VEC; k++) acc[k] = 0.f;
    float ssum = 0.f;

    const __half* hb = g_h16;
    int j = s0;
    // 8-deep unroll: 8 independent src->h / src->as chains in flight
    #pragma unroll 1
    for (; j + 8 <= s1; j += 8) {
        int s[8];
        #pragma unroll
        for (int q = 0; q < 8; q++) s[q] = g_srcs[j + q];
        if constexpr (VEC == 4) {
            uint2 rr[8];
            #pragma unroll
            for (int q = 0; q < 8; q++)
                rr[q] = *reinterpret_cast<const uint2*>(&hb[(size_t)s[q] * DO + lane * 4]);
            float w[8];
            #pragma unroll
            for (int q = 0; q < 8; q++)
                w[q] = __expf(leaky02(g_as[s[q]] + adn));
            #pragma unroll
            for (int q = 0; q < 8; q++) {
                ssum += w[q];
                float2 f0 = __half22float2(*reinterpret_cast<__half2*>(&rr[q].x));
                float2 f1 = __half22float2(*reinterpret_cast<__half2*>(&rr[q].y));
                acc[0] = fmaf(w[q], f0.x, acc[0]);
                acc[1] = fmaf(w[q], f0.y, acc[1]);
                acc[2] = fmaf(w[q], f1.x, acc[2]);
                acc[3] = fmaf(w[q], f1.y, acc[3]);
            }
        } else {
            uint32_t rr[8];
            #pragma unroll
            for (int q = 0; q < 8; q++)
                rr[q] = *reinterpret_cast<const uint32_t*>(&hb[(size_t)s[q] * DO + lane * 2]);
            float w[8];
            #pragma unroll
            for (int q = 0; q < 8; q++)
                w[q] = __expf(leaky02(g_as[s[q]] + adn));
            #pragma unroll
            for (int q = 0; q < 8; q++) {
                ssum += w[q];
                float2 f0 = __half22float2(*reinterpret_cast<__half2*>(&rr[q]));
                acc[0] = fmaf(w[q], f0.x, acc[0]);
                acc[1] = fmaf(w[q], f0.y, acc[1]);
            }
        }
    }
    #pragma unroll 1
    for (; j < s1; ++j) {
        int s = g_srcs[j];
        float w = __expf(leaky02(g_as[s] + adn));
        ssum += w;
        if constexpr (VEC == 4) {
            uint2 r = *reinterpret_cast<const uint2*>(&hb[(size_t)s * DO + lane * 4]);
            float2 f0 = __half22float2(*reinterpret_cast<__half2*>(&r.x));
            float2 f1 = __half22float2(*reinterpret_cast<__half2*>(&r.y));
            acc[0] = fmaf(w, f0.x, acc[0]);
            acc[1] = fmaf(w, f0.y, acc[1]);
            acc[2] = fmaf(w, f1.x, acc[2]);
            acc[3] = fmaf(w, f1.y, acc[3]);
        } else {
            uint32_t r = *reinterpret_cast<const uint32_t*>(&hb[(size_t)s * DO + lane * 2]);
            float2 f0 = __half22float2(*reinterpret_cast<__half2*>(&r));
            acc[0] = fmaf(w, f0.x, acc[0]);
            acc[1] = fmaf(w, f0.y, acc[1]);
        }
    }
    float inv = 1.f / ssum;
    #pragma unroll
    for (int k = 0; k < VEC; k++) {
        float o = fmaf(acc[k], inv, bias[lane * VEC + k]);
        acc[k] = o > 0.f ? o : 0.25f * o;
    }
    float* op = TO_GX ? &g_x[(size_t)node * DO + lane * VEC]
                      : &outp[(size_t)node * DO + lane * VEC];
    if constexpr (VEC == 4)
        *reinterpret_cast<float4*>(op) = make_float4(acc[0], acc[1], acc[2], acc[3]);
    else
        *reinterpret_cast<float2*>(op) = make_float2(acc[0], acc[1]);
}

// ---------------- launch ----------------
extern "C" void kernel_launch(void* const* d_in, const int* in_sizes, int n_in,
                              void* d_out, int out_size) {
    const float* data = (const float*)d_in[0];
    const int*   adj  = (const int*)d_in[1];
    const float* W1  = (const float*)d_in[2];
    const float* as1 = (const float*)d_in[3];
    const float* ad1 = (const float*)d_in[4];
    const float* b1  = (const float*)d_in[5];
    const float* W2  = (const float*)d_in[6];
    const float* as2 = (const float*)d_in[7];
    const float* ad2 = (const float*)d_in[8];
    const float* b2  = (const float*)d_in[9];
    const float* W3  = (const float*)d_in[10];
    const float* as3 = (const float*)d_in[11];
    const float* ad3 = (const float*)d_in[12];
    const float* b3  = (const float*)d_in[13];

    int Nn = in_sizes[0] / 512;
    int Ee = in_sizes[1] / 2;

    static cudaStream_t s2 = nullptr;
    static cudaEvent_t evFork = nullptr, evJoin = nullptr;
    static __nv_bfloat16 *pB1h, *pB1l, *pB2h, *pB2l, *pB3h, *pB3l;
    if (s2 == nullptr) {
        cudaStreamCreateWithFlags(&s2, cudaStreamNonBlocking);
        cudaEventCreateWithFlags(&evFork, cudaEventDisableTiming);
        cudaEventCreateWithFlags(&evJoin, cudaEventDisableTiming);
        void* p;
        cudaGetSymbolAddress(&p, g_B1h); pB1h = (__nv_bfloat16*)p;
        cudaGetSymbolAddress(&p, g_B1l); pB1l = (__nv_bfloat16*)p;
        cudaGetSymbolAddress(&p, g_B2h); pB2h = (__nv_bfloat16*)p;
        cudaGetSymbolAddress(&p, g_B2l); pB2l = (__nv_bfloat16*)p;
        cudaGetSymbolAddress(&p, g_B3h); pB3h = (__nv_bfloat16*)p;
        cudaGetSymbolAddress(&p, g_B3l); pB3l = (__nv_bfloat16*)p;
    }

    const int SM128 = 2 * 128 * 128 + 2 * 128 * 128 + 1024;
    const int SM64  = 2 * 128 * 128 + 2 * 64 * 128 + 1024;
    cudaFuncSetAttribute(mma_gemm_kernel<128>,
                         cudaFuncAttributeMaxDynamicSharedMemorySize, SM128);
    cudaFuncSetAttribute(mma_gemm_kernel<64>,
                         cudaFuncAttributeMaxDynamicSharedMemorySize, SM64);

    const int T = 256;
    int warpGrid = (Nn * 32 + T - 1) / T;
    const int* dst32 = adj + Ee;
    const int* dst64 = adj + 2 * (size_t)Ee;
    int gBlocks = (Nn + 127) / 128;
    int nb = (Nn + SCAN_BS - 1) / SCAN_BS;

    cudaEventRecord(evFork, 0);
    cudaStreamWaitEvent(s2, evFork, 0);
    detect_kernel<<<1, 32, 0, s2>>>(adj);
    init_deg_kernel<<<(Nn + T - 1) / T, T, 0, s2>>>(Nn);

    wsplit_kernel<<<(512 * 128 + T - 1) / T, T>>>(W1, pB1h, pB1l, 512, 128);
    mma_gemm_kernel<128><<<gBlocks, 256, SM128>>>(data, 0, Nn, 512, pB1h, pB1l, as1, ad1);

    count2_kernel<<<(Ee + T - 1) / T, T, 0, s2>>>(dst32, dst64, Ee);
    blockscan_kernel<<<nb, SCAN_BS, 0, s2>>>(Nn);
    bsumscan_kernel<<<1, 512, 0, s2>>>(nb, Nn);
    addoff_kernel<<<(Nn + T - 1) / T, T, 0, s2>>>(Nn);
    scatter2_kernel<<<(Ee + Nn + T - 1) / T, T, 0, s2>>>(adj, dst32, dst64, Ee, Nn);
    wsplit_kernel<<<(128 * 128 + T - 1) / T, T, 0, s2>>>(W2, pB2h, pB2l, 128, 128);
    wsplit_kernel<<<(128 * 64 + T - 1) / T, T, 0, s2>>>(W3, pB3h, pB3l, 128, 64);
    cudaEventRecord(evJoin, s2);

    cudaStreamWaitEvent(0, evJoin, 0);
    aggregate_kernel<128, true><<<warpGrid, T>>>(b1, nullptr, Nn);

    mma_gemm_kernel<128><<<gBlocks, 256, SM128>>>(nullptr, 1, Nn, 128, pB2h, pB2l, as2, ad2);
    aggregate_kernel<128, true><<<warpGrid, T>>>(b2, nullptr, Nn);

    mma_gemm_kernel<64><<<gBlocks, 256, SM64>>>(nullptr, 1, Nn, 128, pB3h, pB3l, as3, ad3);
    aggregate_kernel<64, false><<<warpGrid, T>>>(b3, (float*)d_out, Nn);
}

// round 13
// speedup vs baseline: 1.0110x; 1.0110x over previous
#include <cuda_runtime.h>
#include <cuda_bf16.h>
#include <cuda_fp16.h>
#include <cstdint>

#define MAXN 100000
#define MAXE 1600000
#define MAXT (MAXE + MAXN)

// ---------------- scratch (static device globals; no runtime allocation) ----------------
__device__ __align__(16) __half g_h16[(size_t)MAXN * 128]; // per-layer h = x @ W (fp16)
__device__ __align__(16) float g_x[(size_t)MAXN * 128];    // activations between layers
__device__ float g_as[MAXN];
__device__ float g_ad[MAXN];
__device__ int   g_deg[MAXN];
__device__ int   g_off[MAXN + 1];
__device__ int   g_cur[MAXN];
__device__ int   g_srcs[MAXT];
__device__ int   g_dsts[MAXT];
__device__ float g_w[MAXT];
__device__ int   g_is64;
__device__ int   g_bsum[512];
__device__ __align__(8) __nv_bfloat16 g_B1h[128 * 512], g_B1l[128 * 512];
__device__ __align__(8) __nv_bfloat16 g_B2h[128 * 128], g_B2l[128 * 128];
__device__ __align__(8) __nv_bfloat16 g_B3h[64 * 128],  g_B3l[64 * 128];

// ================= helpers =================
__device__ __forceinline__ uint32_t smem_u32(const void* p) {
    uint32_t a;
    asm("{ .reg .u64 t; cvta.to.shared.u64 t, %1; cvt.u32.u64 %0, t; }" : "=r"(a) : "l"(p));
    return a;
}
__device__ __forceinline__ uint32_t pack_bf16(float a, float b) {
    uint32_t r;
    asm("cvt.rn.bf16x2.f32 %0, %1, %2;" : "=r"(r) : "f"(b), "f"(a));
    return r;
}
__device__ __forceinline__ float bf16_round(float x) {
    return __bfloat162float(__float2bfloat16(x));
}
__device__ __forceinline__ void ldm_x4(uint32_t* r, uint32_t addr) {
    asm volatile("ldmatrix.sync.aligned.m8n8.x4.shared.b16 {%0,%1,%2,%3}, [%4];"
                 : "=r"(r[0]), "=r"(r[1]), "=r"(r[2]), "=r"(r[3]) : "r"(addr));
}
__device__ __forceinline__ void mma_bf16(float* c, const uint32_t* a, const uint32_t* b) {
    asm volatile(
        "mma.sync.aligned.m16n8k16.row.col.f32.bf16.bf16.f32 "
        "{%0,%1,%2,%3},{%4,%5,%6,%7},{%8,%9},{%0,%1,%2,%3};"
        : "+f"(c[0]), "+f"(c[1]), "+f"(c[2]), "+f"(c[3])
        : "r"(a[0]), "r"(a[1]), "r"(a[2]), "r"(a[3]), "r"(b[0]), "r"(b[1]));
}
__device__ __forceinline__ void sts64(uint32_t addr, uint32_t a, uint32_t b) {
    asm volatile("st.shared.v2.u32 [%0], {%1, %2};" :: "r"(addr), "r"(a), "r"(b) : "memory");
}
__device__ __forceinline__ void cp_async8(uint32_t saddr, const void* gptr) {
    asm volatile("cp.async.ca.shared.global [%0], [%1], 8;"
                 :: "r"(saddr), "l"(gptr) : "memory");
}
__device__ __forceinline__ void cp_async_commit() {
    asm volatile("cp.async.commit_group;" ::: "memory");
}
__device__ __forceinline__ void cp_async_wait0() {
    asm volatile("cp.async.wait_group 0;" ::: "memory");
}
__device__ __forceinline__ float leaky02(float v) { return v > 0.f ? v : 0.2f * v; }

// ---------------- adjacency dtype detection ----------------
__global__ void detect_kernel(const int* __restrict__ w) {
    if (threadIdx.x == 0) {
        int all0 = 1;
        #pragma unroll 1
        for (int i = 0; i < 64; i++)
            if (w[2 * i + 1] != 0) { all0 = 0; break; }
        g_is64 = all0;
    }
}

// ---------------- CSR build ----------------
__global__ void init_deg_kernel(int n) {
    int i = blockIdx.x * blockDim.x + threadIdx.x;
    if (i < n) g_deg[i] = 1;  // self-loop
}

__global__ void count2_kernel(const int* __restrict__ dst32,
                              const int* __restrict__ dst64, int e) {
    int i = blockIdx.x * blockDim.x + threadIdx.x;
    if (i >= e) return;
    int is64 = g_is64;
    int d = is64 ? dst64[2 * i] : dst32[i];
    atomicAdd(&g_deg[d], 1);
}

#define SCAN_BS 512
__global__ void blockscan_kernel(int n) {
    __shared__ int sh[SCAN_BS];
    int t = threadIdx.x;
    int i = blockIdx.x * SCAN_BS + t;
    int v = (i < n) ? g_deg[i] : 0;
    sh[t] = v;
    __syncthreads();
    #pragma unroll
    for (int d = 1; d < SCAN_BS; d <<= 1) {
        int x = (t >= d) ? sh[t - d] : 0;
        __syncthreads();
        sh[t] += x;
        __syncthreads();
    }
    if (i < n) g_off[i] = sh[t] - v;
    if (t == SCAN_BS - 1) g_bsum[blockIdx.x] = sh[t];
}

__global__ void bsumscan_kernel(int nb, int n) {
    __shared__ int sh[512];
    int t = threadIdx.x;
    int v = (t < nb) ? g_bsum[t] : 0;
    sh[t] = v;
    __syncthreads();
    #pragma unroll
    for (int d = 1; d < 512; d <<= 1) {
        int x = (t >= d) ? sh[t - d] : 0;
        __syncthreads();
        sh[t] += x;
        __syncthreads();
    }
    if (t < nb) g_bsum[t] = sh[t] - v;
    if (t == 511) g_off[n] = sh[511];
}

__global__ void addoff_kernel(int n) {
    int i = blockIdx.x * blockDim.x + threadIdx.x;
    if (i < n) {
        int o = g_off[i] + g_bsum[i >> 9];
        g_off[i] = o;
        g_cur[i] = o;
    }
}

__global__ void scatter2_kernel(const int* __restrict__ src,
                                const int* __restrict__ dst32,
                                const int* __restrict__ dst64, int e, int n) {
    int i = blockIdx.x * blockDim.x + threadIdx.x;
    int is64 = g_is64;
    if (i < e) {
        int d = is64 ? dst64[2 * i] : dst32[i];
        int s = is64 ? src[2 * i] : src[i];
        int p = atomicAdd(&g_cur[d], 1);
        g_srcs[p] = s;
        g_dsts[p] = d;
    } else if (i < e + n) {
        int v = i - e;
        int p = atomicAdd(&g_cur[v], 1);
        g_srcs[p] = v;
        g_dsts[p] = v;
    }
}

// ---------------- W transpose + bf16 hi/lo split ----------------
__global__ void wsplit_kernel(const float* __restrict__ W,
                              __nv_bfloat16* __restrict__ Bh,
                              __nv_bfloat16* __restrict__ Bl, int K, int Nd) {
    int i = blockIdx.x * blockDim.x + threadIdx.x;
    if (i >= K * Nd) return;
    int k = i / Nd, nn = i % Nd;
    float x = W[i];
    float h = bf16_round(x);
    Bh[(size_t)nn * K + k] = __float2bfloat16(h);
    Bl[(size_t)nn * K + k] = __float2bfloat16(x - h);
}

// ---------------- edge weights: w[i] = exp(leaky(as[src]+ad[dst])), edge-parallel ----------------
__global__ void edgew_kernel(int t) {
    int i = blockIdx.x * blockDim.x + threadIdx.x;
    if (i >= t) return;
    int s = g_srcs[i];
    int d = g_dsts[i];
    g_w[i] = __expf(leaky02(g_as[s] + g_ad[d]));
}

// ---------------- mma.sync bf16-split GEMM + fused alpha dots ----------------
// B double-buffered via cp.async issued before compute; A single-buffered.
template <int NDIM>
__global__ void __launch_bounds__(256, 2)
mma_gemm_kernel(const float* __restrict__ Ain, int useGX, int M, int K,
                const __nv_bfloat16* __restrict__ Bhi,
                const __nv_bfloat16* __restrict__ Blo,
                const float* __restrict__ a_src, const float* __restrict__ a_dst) {
    constexpr int ABYTES = 128 * 128;          // 16KB per A buffer (hi or lo)
    constexpr int BBYTES = NDIM * 128;         // per B buffer per stage
    constexpr int BP = NDIM / 16;
    constexpr int MT = (NDIM == 128) ? 2 : 1;
    constexpr int MROWS = MT * 16;
    extern __shared__ char smraw[];
    char* smem = (char*)(((uintptr_t)smraw + 1023) & ~(uintptr_t)1023);
    uint32_t aHiB = smem_u32(smem);
    uint32_t aLoB = aHiB + ABYTES;
    // B stages: [stage][hi/lo]
    uint32_t bBase = aHiB + 2 * ABYTES;

    const float* A = useGX ? g_x : Ain;
    const int tid = threadIdx.x, wid = tid >> 5, lane = tid & 31;
    const int rowBase = blockIdx.x * 128;
    const int wm = (NDIM == 128) ? (wid & 3) : wid;
    const int wn = (NDIM == 128) ? (wid >> 2) : 0;

    float acc[MT][8][4];
    #pragma unroll
    for (int mt = 0; mt < MT; mt++)
        #pragma unroll
        for (int nt = 0; nt < 8; nt++)
            #pragma unroll
            for (int q = 0; q < 4; q++) acc[mt][nt][q] = 0.f;

    const int aRow = wm * MROWS + (lane & 7) + ((lane >> 3) & 1) * 8;
    const uint32_t aRowOff = (uint32_t)aRow * 128;
    const uint32_t aSwz = (uint32_t)(lane & 7) << 4;
    const uint32_t aHalf = ((lane >> 4) & 1) * 16;
    const uint32_t bRow4 = (uint32_t)((lane & 7) | ((lane >> 4) << 3));
    const uint32_t bRowOff4 = (uint32_t)(wn * 64 + bRow4) * 128;
    const uint32_t bSwz4 = (uint32_t)(lane & 7) << 4;
    const uint32_t bHalf4 = ((lane >> 3) & 1) * 16;

    const int sr = tid >> 4;
    const int cg = (tid & 15) * 4;
    const uint32_t stCol = (uint32_t)(cg * 2);
    const uint32_t stOffBase[8] = {
        (0u * 16 + (uint32_t)sr) * 128 + (stCol ^ (((0u * 16 + (uint32_t)sr) & 7) << 4)),
        (1u * 16 + (uint32_t)sr) * 128 + (stCol ^ (((1u * 16 + (uint32_t)sr) & 7) << 4)),
        (2u * 16 + (uint32_t)sr) * 128 + (stCol ^ (((2u * 16 + (uint32_t)sr) & 7) << 4)),
        (3u * 16 + (uint32_t)sr) * 128 + (stCol ^ (((3u * 16 + (uint32_t)sr) & 7) << 4)),
        (4u * 16 + (uint32_t)sr) * 128 + (stCol ^ (((4u * 16 + (uint32_t)sr) & 7) << 4)),
        (5u * 16 + (uint32_t)sr) * 128 + (stCol ^ (((5u * 16 + (uint32_t)sr) & 7) << 4)),
        (6u * 16 + (uint32_t)sr) * 128 + (stCol ^ (((6u * 16 + (uint32_t)sr) & 7) << 4)),
        (7u * 16 + (uint32_t)sr) * 128 + (stCol ^ (((7u * 16 + (uint32_t)sr) & 7) << 4)),
    };

    const int nChunks = K >> 6;

    // ---- prologue: stage chunk 0 ----
    float4 pref[8];
    #pragma unroll
    for (int p = 0; p < 8; p++) {
        int gr = rowBase + p * 16 + sr;
        pref[p] = make_float4(0.f, 0.f, 0.f, 0.f);
        if (gr < M)
            pref[p] = *reinterpret_cast<const float4*>(&A[(size_t)gr * K + cg]);
    }
    #pragma unroll
    for (int p = 0; p < BP; p++) {
        int r = p * 16 + sr;
        uint32_t off = (uint32_t)r * 128 + (stCol ^ ((uint32_t)(r & 7) << 4));
        cp_async8(bBase + off, &Bhi[(size_t)r * K + cg]);
        cp_async8(bBase + BBYTES + off, &Blo[(size_t)r * K + cg]);
    }
    cp_async_commit();
    #pragma unroll
    for (int p = 0; p < 8; p++) {
        float4 v = pref[p];
        float h0 = bf16_round(v.x), h1 = bf16_round(v.y);
        float h2 = bf16_round(v.z), h3 = bf16_round(v.w);
        uint32_t off = stOffBase[p];
        sts64(aHiB + off, pack_bf16(v.x, v.y), pack_bf16(v.z, v.w));
        sts64(aLoB + off, pack_bf16(v.x - h0, v.y - h1), pack_bf16(v.z - h2, v.w - h3));
    }
    cp_async_wait0();
    __syncthreads();

    for (int c = 0; c < nChunks; c++) {
        const uint32_t bCur = bBase + (uint32_t)(c & 1) * 2 * BBYTES;
        const uint32_t bNxt = bBase + (uint32_t)((c + 1) & 1) * 2 * BBYTES;
        const bool more = (c + 1 < nChunks);
        // ---- issue B(c+1) cp.async + A(c+1) register prefetch (hidden under MMA) ----
        if (more) {
            const int k1 = (c + 1) << 6;
            #pragma unroll
            for (int p = 0; p < BP; p++) {
                int r = p * 16 + sr;
                uint32_t off = (uint32_t)r * 128 + (stCol ^ ((uint32_t)(r & 7) << 4));
                cp_async8(bNxt + off, &Bhi[(size_t)r * K + k1 + cg]);
                cp_async8(bNxt + BBYTES + off, &Blo[(size_t)r * K + k1 + cg]);
            }
            cp_async_commit();
            #pragma unroll
            for (int p = 0; p < 8; p++) {
                int gr = rowBase + p * 16 + sr;
                pref[p] = make_float4(0.f, 0.f, 0.f, 0.f);
                if (gr < M)
                    pref[p] = *reinterpret_cast<const float4*>(&A[(size_t)gr * K + k1 + cg]);
            }
        }

        // ---- compute chunk c ----
        #pragma unroll
        for (int kt = 0; kt < 4; kt++) {
            uint32_t kc = (uint32_t)kt * 32;
            uint32_t aoff = aRowOff + ((kc + aHalf) ^ aSwz);
            uint32_t ahi[MT][4], alo[MT][4];
            #pragma unroll
            for (int mt = 0; mt < MT; mt++) {
                ldm_x4(ahi[mt], aHiB + aoff + (uint32_t)mt * 2048);
                ldm_x4(alo[mt], aLoB + aoff + (uint32_t)mt * 2048);
            }
            uint32_t bcol = (kc + bHalf4) ^ bSwz4;
            #pragma unroll
            for (int np = 0; np < 4; np++) {
                uint32_t boff = bRowOff4 + (uint32_t)np * 2048 + bcol;
                uint32_t bhi[4], blo[4];
                ldm_x4(bhi, bCur + boff);
                ldm_x4(blo, bCur + BBYTES + boff);
                #pragma unroll
                for (int mt = 0; mt < MT; mt++) {
                    mma_bf16(acc[mt][2 * np],     ahi[mt], &bhi[0]);
                    mma_bf16(acc[mt][2 * np],     ahi[mt], &blo[0]);
                    mma_bf16(acc[mt][2 * np],     alo[mt], &bhi[0]);
                    mma_bf16(acc[mt][2 * np + 1], ahi[mt], &bhi[2]);
                    mma_bf16(acc[mt][2 * np + 1], ahi[mt], &blo[2]);
                    mma_bf16(acc[mt][2 * np + 1], alo[mt], &bhi[2]);
                }
            }
        }
        __syncthreads();   // all reads of A stage + B[cur] done

        if (more) {
            // ---- stage A(c+1) into the (single) A buffers ----
            #pragma unroll
            for (int p = 0; p < 8; p++) {
                float4 v = pref[p];
                float h0 = bf16_round(v.x), h1 = bf16_round(v.y);
                float h2 = bf16_round(v.z), h3 = bf16_round(v.w);
                uint32_t off = stOffBase[p];
                sts64(aHiB + off, pack_bf16(v.x, v.y), pack_bf16(v.z, v.w));
                sts64(aLoB + off, pack_bf16(v.x - h0, v.y - h1), pack_bf16(v.z - h2, v.w - h3));
            }
            cp_async_wait0();
            __syncthreads();
        }
    }

    // ---- epilogue: write h (fp16) + alpha dot partials ----
    int r0 = rowBase + wm * MROWS + (lane >> 2);
    int colb = (lane & 3) * 2;
    float sp[MT][2], dp[MT][2];
    #pragma unroll
    for (int mt = 0; mt < MT; mt++) { sp[mt][0] = sp[mt][1] = dp[mt][0] = dp[mt][1] = 0.f; }

    #pragma unroll
    for (int mt = 0; mt < MT; mt++) {
        int rA = r0 + mt * 16;
        #pragma unroll
        for (int nt = 0; nt < 8; nt++) {
            int col = wn * 64 + nt * 8 + colb;
            float a0 = a_src[col], a1 = a_src[col + 1];
            float e0 = a_dst[col], e1 = a_dst[col + 1];
            sp[mt][0] = fmaf(acc[mt][nt][0], a0, fmaf(acc[mt][nt][1], a1, sp[mt][0]));
            dp[mt][0] = fmaf(acc[mt][nt][0], e0, fmaf(acc[mt][nt][1], e1, dp[mt][0]));
            sp[mt][1] = fmaf(acc[mt][nt][2], a0, fmaf(acc[mt][nt][3], a1, sp[mt][1]));
            dp[mt][1] = fmaf(acc[mt][nt][2], e0, fmaf(acc[mt][nt][3], e1, dp[mt][1]));
            if (rA < M)
                *reinterpret_cast<__half2*>(&g_h16[(size_t)rA * NDIM + col]) =
                    __floats2half2_rn(acc[mt][nt][0], acc[mt][nt][1]);
            if (rA + 8 < M)
                *reinterpret_cast<__half2*>(&g_h16[(size_t)(rA + 8) * NDIM + col]) =
                    __floats2half2_rn(acc[mt][nt][2], acc[mt][nt][3]);
        }
    }
    #pragma unroll
    for (int o = 1; o <= 2; o <<= 1) {
        #pragma unroll
        for (int mt = 0; mt < MT; mt++) {
            sp[mt][0] += __shfl_xor_sync(0xffffffffu, sp[mt][0], o);
            dp[mt][0] += __shfl_xor_sync(0xffffffffu, dp[mt][0], o);
            sp[mt][1] += __shfl_xor_sync(0xffffffffu, sp[mt][1], o);
            dp[mt][1] += __shfl_xor_sync(0xffffffffu, dp[mt][1], o);
        }
    }

    if constexpr (NDIM == 128) {
        float* sal = (float*)smem;   // reuse A region
        __syncthreads();
        if ((lane & 3) == 0) {
            int lr = wm * MROWS + (lane >> 2);
            #pragma unroll
            for (int mt = 0; mt < MT; mt++) {
                #pragma unroll
                for (int rh = 0; rh < 2; rh++) {
                    int row = lr + mt * 16 + rh * 8;
                    sal[row * 4 + wn * 2]     = (rh == 0) ? sp[mt][0] : sp[mt][1];
                    sal[row * 4 + wn * 2 + 1] = (rh == 0) ? dp[mt][0] : dp[mt][1];
                }
            }
        }
        __syncthreads();
        if (tid < 128) {
            int gr = rowBase + tid;
            if (gr < M) {
                g_as[gr] = sal[tid * 4] + sal[tid * 4 + 2];
                g_ad[gr] = sal[tid * 4 + 1] + sal[tid * 4 + 3];
            }
        }
    } else {
        if ((lane & 3) == 0) {
            if (r0 < M)     { g_as[r0] = sp[0][0];     g_ad[r0] = dp[0][0]; }
            if (r0 + 8 < M) { g_as[r0 + 8] = sp[0][1]; g_ad[r0 + 8] = dp[0][1]; }
        }
    }
}

// ---------------- aggregation with precomputed edge weights, fp16 h gather ----------------
template <int DO, bool TO_GX>
__global__ void aggregate_kernel(const float* __restrict__ bias,
                                 float* __restrict__ outp, int n) {
    constexpr int VEC = DO / 32;
    int node = (blockIdx.x * blockDim.x + threadIdx.x) >> 5;
    int lane = threadIdx.x & 31;
    if (node >= n) return;
    int s0 = g_off[node], s1 = g_off[node + 1];

    float acc[VEC];
    #pragma unroll
    for (int k = 0; k < VEC; k++) acc[k] = 0.f;
    float ssum = 0.f;

    const __half* hb = g_h16;
    int j = s0;
    #pragma unroll 1
    for (; j + 8 <= s1; j += 8) {
        int s[8];
        float w[8];
        #pragma unroll
        for (int q = 0; q < 8; q++) { s[q] = g_srcs[j + q]; w[q] = g_w[j + q]; }
        if constexpr (VEC == 4) {
            uint2 rr[8];
            #pragma unroll
            for (int q = 0; q < 8; q++)
                rr[q] = *reinterpret_cast<const uint2*>(&hb[(size_t)s[q] * DO + lane * 4]);
            #pragma unroll
            for (int q = 0; q < 8; q++) {
                ssum += w[q];
                float2 f0 = __half22float2(*reinterpret_cast<__half2*>(&rr[q].x));
                float2 f1 = __half22float2(*reinterpret_cast<__half2*>(&rr[q].y));
                acc[0] = fmaf(w[q], f0.x, acc[0]);
                acc[1] = fmaf(w[q], f0.y, acc[1]);
                acc[2] = fmaf(w[q], f1.x, acc[2]);
                acc[3] = fmaf(w[q], f1.y, acc[3]);
            }
        } else {
            uint32_t rr[8];
            #pragma unroll
            for (int q = 0; q < 8; q++)
                rr[q] = *reinterpret_cast<const uint32_t*>(&hb[(size_t)s[q] * DO + lane * 2]);
            #pragma unroll
            for (int q = 0; q < 8; q++) {
                ssum += w[q];
                float2 f0 = __half22float2(*reinterpret_cast<__half2*>(&rr[q]));
                acc[0] = fmaf(w[q], f0.x, acc[0]);
                acc[1] = fmaf(w[q], f0.y, acc[1]);
            }
        }
    }
    #pragma unroll 1
    for (; j < s1; ++j) {
        int s = g_srcs[j];
        float w = g_w[j];
        ssum += w;
        if constexpr (VEC == 4) {
            uint2 r = *reinterpret_cast<const uint2*>(&hb[(size_t)s * DO + lane * 4]);
            float2 f0 = __half22float2(*reinterpret_cast<__half2*>(&r.x));
            float2 f1 = __half22float2(*reinterpret_cast<__half2*>(&r.y));
            acc[0] = fmaf(w, f0.x, acc[0]);
            acc[1] = fmaf(w, f0.y, acc[1]);
            acc[2] = fmaf(w, f1.x, acc[2]);
            acc[3] = fmaf(w, f1.y, acc[3]);
        } else {
            uint32_t r = *reinterpret_cast<const uint32_t*>(&hb[(size_t)s * DO + lane * 2]);
            float2 f0 = __half22float2(*reinterpret_cast<__half2*>(&r));
            acc[0] = fmaf(w, f0.x, acc[0]);
            acc[1] = fmaf(w, f0.y, acc[1]);
        }
    }
    float inv = 1.f / ssum;
    #pragma unroll
    for (int k = 0; k < VEC; k++) {
        float o = fmaf(acc[k], inv, bias[lane * VEC + k]);
        acc[k] = o > 0.f ? o : 0.25f * o;
    }
    float* op = TO_GX ? &g_x[(size_t)node * DO + lane * VEC]
                      : &outp[(size_t)node * DO + lane * VEC];
    if constexpr (VEC == 4)
        *reinterpret_cast<float4*>(op) = make_float4(acc[0], acc[1], acc[2], acc[3]);
    else
        *reinterpret_cast<float2*>(op) = make_float2(acc[0], acc[1]);
}

// ---------------- launch ----------------
extern "C" void kernel_launch(void* const* d_in, const int* in_sizes, int n_in,
                              void* d_out, int out_size) {
    const float* data = (const float*)d_in[0];
    const int*   adj  = (const int*)d_in[1];
    const float* W1  = (const float*)d_in[2];
    const float* as1 = (const float*)d_in[3];
    const float* ad1 = (const float*)d_in[4];
    const float* b1  = (const float*)d_in[5];
    const float* W2  = (const float*)d_in[6];
    const float* as2 = (const float*)d_in[7];
    const float* ad2 = (const float*)d_in[8];
    const float* b2  = (const float*)d_in[9];
    const float* W3  = (const float*)d_in[10];
    const float* as3 = (const float*)d_in[11];
    const float* ad3 = (const float*)d_in[12];
    const float* b3  = (const float*)d_in[13];

    int Nn = in_sizes[0] / 512;
    int Ee = in_sizes[1] / 2;
    int Te = Ee + Nn;                      // total CSR entries

    static cudaStream_t s2 = nullptr;
    static cudaEvent_t evFork = nullptr, evJoin = nullptr;
    static __nv_bfloat16 *pB1h, *pB1l, *pB2h, *pB2l, *pB3h, *pB3l;
    if (s2 == nullptr) {
        cudaStreamCreateWithFlags(&s2, cudaStreamNonBlocking);
        cudaEventCreateWithFlags(&evFork, cudaEventDisableTiming);
        cudaEventCreateWithFlags(&evJoin, cudaEventDisableTiming);
        void* p;
        cudaGetSymbolAddress(&p, g_B1h); pB1h = (__nv_bfloat16*)p;
        cudaGetSymbolAddress(&p, g_B1l); pB1l = (__nv_bfloat16*)p;
        cudaGetSymbolAddress(&p, g_B2h); pB2h = (__nv_bfloat16*)p;
        cudaGetSymbolAddress(&p, g_B2l); pB2l = (__nv_bfloat16*)p;
        cudaGetSymbolAddress(&p, g_B3h); pB3h = (__nv_bfloat16*)p;
        cudaGetSymbolAddress(&p, g_B3l); pB3l = (__nv_bfloat16*)p;
    }

    // smem: A hi/lo (32KB) + B 2 stages x hi/lo
    const int SM128 = 2 * 128 * 128 + 4 * 128 * 128 / 2 * 2 + 1024;  // 32K + 64K + pad
    const int SM64  = 2 * 128 * 128 + 4 * 64 * 128 + 1024;           // 32K + 32K + pad
    cudaFuncSetAttribute(mma_gemm_kernel<128>,
                         cudaFuncAttributeMaxDynamicSharedMemorySize, SM128);
    cudaFuncSetAttribute(mma_gemm_kernel<64>,
                         cudaFuncAttributeMaxDynamicSharedMemorySize, SM64);

    const int T = 256;
    int warpGrid = (Nn * 32 + T - 1) / T;
    int edgeGrid = (Te + T - 1) / T;
    const int* dst32 = adj + Ee;
    const int* dst64 = adj + 2 * (size_t)Ee;
    int gBlocks = (Nn + 127) / 128;
    int nb = (Nn + SCAN_BS - 1) / SCAN_BS;

    cudaEventRecord(evFork, 0);
    cudaStreamWaitEvent(s2, evFork, 0);
    detect_kernel<<<1, 32, 0, s2>>>(adj);
    init_deg_kernel<<<(Nn + T - 1) / T, T, 0, s2>>>(Nn);

    wsplit_kernel<<<(512 * 128 + T - 1) / T, T>>>(W1, pB1h, pB1l, 512, 128);
    mma_gemm_kernel<128><<<gBlocks, 256, SM128>>>(data, 0, Nn, 512, pB1h, pB1l, as1, ad1);

    count2_kernel<<<(Ee + T - 1) / T, T, 0, s2>>>(dst32, dst64, Ee);
    blockscan_kernel<<<nb, SCAN_BS, 0, s2>>>(Nn);
    bsumscan_kernel<<<1, 512, 0, s2>>>(nb, Nn);
    addoff_kernel<<<(Nn + T - 1) / T, T, 0, s2>>>(Nn);
    scatter2_kernel<<<(Ee + Nn + T - 1) / T, T, 0, s2>>>(adj, dst32, dst64, Ee, Nn);
    wsplit_kernel<<<(128 * 128 + T - 1) / T, T, 0, s2>>>(W2, pB2h, pB2l, 128, 128);
    wsplit_kernel<<<(128 * 64 + T - 1) / T, T, 0, s2>>>(W3, pB3h, pB3l, 128, 64);
    cudaEventRecord(evJoin, s2);

    cudaStreamWaitEvent(0, evJoin, 0);
    edgew_kernel<<<edgeGrid, T>>>(Te);
    aggregate_kernel<128, true><<<warpGrid, T>>>(b1, nullptr, Nn);

    mma_gemm_kernel<128><<<gBlocks, 256, SM128>>>(nullptr, 1, Nn, 128, pB2h, pB2l, as2, ad2);
    edgew_kernel<<<edgeGrid, T>>>(Te);
    aggregate_kernel<128, true><<<warpGrid, T>>>(b2, nullptr, Nn);

    mma_gemm_kernel<64><<<gBlocks, 256, SM64>>>(nullptr, 1, Nn, 128, pB3h, pB3l, as3, ad3);
    edgew_kernel<<<edgeGrid, T>>>(Te);
    aggregate_kernel<64, false><<<warpGrid, T>>>(b3, (float*)d_out, Nn);
}

// round 14
// speedup vs baseline: 1.1335x; 1.1212x over previous
#include <cuda_runtime.h>
#include <cuda_fp16.h>
#include <cstdint>

#define MAXN 100000
#define MAXE 1600000
#define MAXT (MAXE + MAXN)

// ---------------- scratch (static device globals; no runtime allocation) ----------------
__device__ __align__(16) __half g_h16[(size_t)MAXN * 128]; // per-layer h = x @ W (fp16)
__device__ __align__(16) float g_x[(size_t)MAXN * 128];    // activations between layers
__device__ float g_as[MAXN];
__device__ float g_ad[MAXN];
__device__ int   g_deg[MAXN];
__device__ int   g_off[MAXN + 1];
__device__ int   g_cur[MAXN];
__device__ int   g_srcs[MAXT];
__device__ int   g_dsts[MAXT];
__device__ float g_w[MAXT];
__device__ int   g_is64;
__device__ int   g_bsum[512];
// per-layer W^T fp16 hi/lo splits
__device__ __align__(8) __half g_B1h[128 * 512], g_B1l[128 * 512];
__device__ __align__(8) __half g_B2h[128 * 128], g_B2l[128 * 128];
__device__ __align__(8) __half g_B3h[64 * 128],  g_B3l[64 * 128];

// ================= helpers =================
__device__ __forceinline__ uint32_t smem_u32(const void* p) {
    uint32_t a;
    asm("{ .reg .u64 t; cvta.to.shared.u64 t, %1; cvt.u32.u64 %0, t; }" : "=r"(a) : "l"(p));
    return a;
}
__device__ __forceinline__ uint32_t pack_f16(float a, float b) {  // a -> low, b -> high
    uint32_t r;
    asm("cvt.rn.f16x2.f32 %0, %1, %2;" : "=r"(r) : "f"(b), "f"(a));
    return r;
}
__device__ __forceinline__ void ldm_x4(uint32_t* r, uint32_t addr) {
    asm volatile("ldmatrix.sync.aligned.m8n8.x4.shared.b16 {%0,%1,%2,%3}, [%4];"
                 : "=r"(r[0]), "=r"(r[1]), "=r"(r[2]), "=r"(r[3]) : "r"(addr));
}
__device__ __forceinline__ void mma_f16(float* c, const uint32_t* a, const uint32_t* b) {
    asm volatile(
        "mma.sync.aligned.m16n8k16.row.col.f32.f16.f16.f32 "
        "{%0,%1,%2,%3},{%4,%5,%6,%7},{%8,%9},{%0,%1,%2,%3};"
        : "+f"(c[0]), "+f"(c[1]), "+f"(c[2]), "+f"(c[3])
        : "r"(a[0]), "r"(a[1]), "r"(a[2]), "r"(a[3]), "r"(b[0]), "r"(b[1]));
}
__device__ __forceinline__ void sts64(uint32_t addr, uint32_t a, uint32_t b) {
    asm volatile("st.shared.v2.u32 [%0], {%1, %2};" :: "r"(addr), "r"(a), "r"(b) : "memory");
}
__device__ __forceinline__ void cp_async8(uint32_t saddr, const void* gptr) {
    asm volatile("cp.async.ca.shared.global [%0], [%1], 8;"
                 :: "r"(saddr), "l"(gptr) : "memory");
}
__device__ __forceinline__ void cp_async_commit_wait() {
    asm volatile("cp.async.commit_group;" ::: "memory");
    asm volatile("cp.async.wait_group 0;" ::: "memory");
}
__device__ __forceinline__ float leaky02(float v) { return v > 0.f ? v : 0.2f * v; }

// ---------------- adjacency dtype detection ----------------
__global__ void detect_kernel(const int* __restrict__ w) {
    if (threadIdx.x == 0) {
        int all0 = 1;
        #pragma unroll 1
        for (int i = 0; i < 64; i++)
            if (w[2 * i + 1] != 0) { all0 = 0; break; }
        g_is64 = all0;
    }
}

// ---------------- CSR build ----------------
__global__ void init_deg_kernel(int n) {
    int i = blockIdx.x * blockDim.x + threadIdx.x;
    if (i < n) g_deg[i] = 1;  // self-loop
}

__global__ void count2_kernel(const int* __restrict__ dst32,
                              const int* __restrict__ dst64, int e) {
    int i = blockIdx.x * blockDim.x + threadIdx.x;
    if (i >= e) return;
    int is64 = g_is64;
    int d = is64 ? dst64[2 * i] : dst32[i];
    atomicAdd(&g_deg[d], 1);
}

#define SCAN_BS 512
__global__ void blockscan_kernel(int n) {
    __shared__ int sh[SCAN_BS];
    int t = threadIdx.x;
    int i = blockIdx.x * SCAN_BS + t;
    int v = (i < n) ? g_deg[i] : 0;
    sh[t] = v;
    __syncthreads();
    #pragma unroll
    for (int d = 1; d < SCAN_BS; d <<= 1) {
        int x = (t >= d) ? sh[t - d] : 0;
        __syncthreads();
        sh[t] += x;
        __syncthreads();
    }
    if (i < n) g_off[i] = sh[t] - v;
    if (t == SCAN_BS - 1) g_bsum[blockIdx.x] = sh[t];
}

__global__ void bsumscan_kernel(int nb, int n) {
    __shared__ int sh[512];
    int t = threadIdx.x;
    int v = (t < nb) ? g_bsum[t] : 0;
    sh[t] = v;
    __syncthreads();
    #pragma unroll
    for (int d = 1; d < 512; d <<= 1) {
        int x = (t >= d) ? sh[t - d] : 0;
        __syncthreads();
        sh[t] += x;
        __syncthreads();
    }
    if (t < nb) g_bsum[t] = sh[t] - v;
    if (t == 511) g_off[n] = sh[511];
}

__global__ void addoff_kernel(int n) {
    int i = blockIdx.x * blockDim.x + threadIdx.x;
    if (i < n) {
        int o = g_off[i] + g_bsum[i >> 9];
        g_off[i] = o;
        g_cur[i] = o;
    }
}

__global__ void scatter2_kernel(const int* __restrict__ src,
                                const int* __restrict__ dst32,
                                const int* __restrict__ dst64, int e, int n) {
    int i = blockIdx.x * blockDim.x + threadIdx.x;
    int is64 = g_is64;
    if (i < e) {
        int d = is64 ? dst64[2 * i] : dst32[i];
        int s = is64 ? src[2 * i] : src[i];
        int p = atomicAdd(&g_cur[d], 1);
        g_srcs[p] = s;
        g_dsts[p] = d;
    } else if (i < e + n) {
        int v = i - e;
        int p = atomicAdd(&g_cur[v], 1);
        g_srcs[p] = v;
        g_dsts[p] = v;
    }
}

// ---------------- W transpose + fp16 hi/lo split ----------------
__global__ void wsplit_kernel(const float* __restrict__ W,
                              __half* __restrict__ Bh,
                              __half* __restrict__ Bl, int K, int Nd) {
    int i = blockIdx.x * blockDim.x + threadIdx.x;
    if (i >= K * Nd) return;
    int k = i / Nd, nn = i % Nd;
    float x = W[i];
    __half h = __float2half_rn(x);
    Bh[(size_t)nn * K + k] = h;
    Bl[(size_t)nn * K + k] = __float2half_rn(x - __half2float(h));
}

// ---------------- edge weights: w[i] = exp(leaky(as[src]+ad[dst])), edge-parallel ----------------
__global__ void edgew_kernel(int t) {
    int i = blockIdx.x * blockDim.x + threadIdx.x;
    if (i >= t) return;
    int s = g_srcs[i];
    int d = g_dsts[i];
    g_w[i] = __expf(leaky02(g_as[s] + g_ad[d]));
}

// ---------------- mma.sync 2-term fp16-split GEMM + fused alpha dots ----------------
// A in fp16 (hi only); W pre-split fp16 hi/lo. D = Ah*Bh + Ah*Bl (fp32 accum).
// NDIM=128: warp grid 4x2, warp tile 32x64. Single-stage B via cp.async.
template <int NDIM>
__global__ void __launch_bounds__(256, 2)
mma_gemm_kernel(const float* __restrict__ Ain, int useGX, int M, int K,
                const __half* __restrict__ Bhi,
                const __half* __restrict__ Blo,
                const float* __restrict__ a_src, const float* __restrict__ a_dst) {
    constexpr int ABYTES = 128 * 128;          // 16KB, A hi tile
    constexpr int BBYTES = NDIM * 128;
    constexpr int BP = NDIM / 16;
    constexpr int MT = (NDIM == 128) ? 2 : 1;
    constexpr int MROWS = MT * 16;
    extern __shared__ char smraw[];
    char* smem = (char*)(((uintptr_t)smraw + 1023) & ~(uintptr_t)1023);
    uint32_t aHiB = smem_u32(smem);
    uint32_t bHiB = aHiB + ABYTES;
    uint32_t bLoB = bHiB + BBYTES;

    const float* A = useGX ? g_x : Ain;
    const int tid = threadIdx.x, wid = tid >> 5, lane = tid & 31;
    const int rowBase = blockIdx.x * 128;
    const int wm = (NDIM == 128) ? (wid & 3) : wid;
    const int wn = (NDIM == 128) ? (wid >> 2) : 0;

    float acc[MT][8][4];
    #pragma unroll
    for (int mt = 0; mt < MT; mt++)
        #pragma unroll
        for (int nt = 0; nt < 8; nt++)
            #pragma unroll
            for (int q = 0; q < 4; q++) acc[mt][nt][q] = 0.f;

    const int aRow = wm * MROWS + (lane & 7) + ((lane >> 3) & 1) * 8;
    const uint32_t aRowOff = (uint32_t)aRow * 128;
    const uint32_t aSwz = (uint32_t)(lane & 7) << 4;
    const uint32_t aHalf = ((lane >> 4) & 1) * 16;
    const uint32_t bRow4 = (uint32_t)((lane & 7) | ((lane >> 4) << 3));
    const uint32_t bRowOff4 = (uint32_t)(wn * 64 + bRow4) * 128;
    const uint32_t bSwz4 = (uint32_t)(lane & 7) << 4;
    const uint32_t bHalf4 = ((lane >> 3) & 1) * 16;

    const int sr = tid >> 4;
    const int cg = (tid & 15) * 4;
    const uint32_t stCol = (uint32_t)(cg * 2);

    const int nChunks = K >> 6;

    float4 pref[8];
    #pragma unroll
    for (int p = 0; p < 8; p++) {
        int gr = rowBase + p * 16 + sr;
        pref[p] = make_float4(0.f, 0.f, 0.f, 0.f);
        if (gr < M)
            pref[p] = *reinterpret_cast<const float4*>(&A[(size_t)gr * K + cg]);
    }

    for (int c = 0; c < nChunks; c++) {
        const int k0 = c << 6;
        // ---- B staging via cp.async ----
        #pragma unroll
        for (int p = 0; p < BP; p++) {
            int r = p * 16 + sr;
            uint32_t off = (uint32_t)r * 128 + (stCol ^ ((uint32_t)(r & 7) << 4));
            cp_async8(bHiB + off, &Bhi[(size_t)r * K + k0 + cg]);
            cp_async8(bLoB + off, &Blo[(size_t)r * K + k0 + cg]);
        }
        // ---- stage A (fp16 hi only, 8B vector STS) ----
        #pragma unroll
        for (int p = 0; p < 8; p++) {
            int r = p * 16 + sr;
            float4 v = pref[p];
            uint32_t off = (uint32_t)r * 128 + (stCol ^ ((uint32_t)(r & 7) << 4));
            sts64(aHiB + off, pack_f16(v.x, v.y), pack_f16(v.z, v.w));
        }
        cp_async_commit_wait();
        __syncthreads();

        // ---- prefetch A chunk c+1 (overlaps with MMA) ----
        if (c + 1 < nChunks) {
            const int k1 = (c + 1) << 6;
            #pragma unroll
            for (int p = 0; p < 8; p++) {
                int gr = rowBase + p * 16 + sr;
                pref[p] = make_float4(0.f, 0.f, 0.f, 0.f);
                if (gr < M)
                    pref[p] = *reinterpret_cast<const float4*>(&A[(size_t)gr * K + k1 + cg]);
            }
        }

        // ---- compute: 2-term (Ah*Bh + Ah*Bl) ----
        #pragma unroll
        for (int kt = 0; kt < 4; kt++) {
            uint32_t kc = (uint32_t)kt * 32;
            uint32_t aoff = aRowOff + ((kc + aHalf) ^ aSwz);
            uint32_t ahi[MT][4];
            #pragma unroll
            for (int mt = 0; mt < MT; mt++)
                ldm_x4(ahi[mt], aHiB + aoff + (uint32_t)mt * 2048);
            uint32_t bcol = (kc + bHalf4) ^ bSwz4;
            #pragma unroll
            for (int np = 0; np < 4; np++) {
                uint32_t boff = bRowOff4 + (uint32_t)np * 2048 + bcol;
                uint32_t bhi[4], blo[4];
                ldm_x4(bhi, bHiB + boff);
                ldm_x4(blo, bLoB + boff);
                #pragma unroll
                for (int mt = 0; mt < MT; mt++) {
                    mma_f16(acc[mt][2 * np],     ahi[mt], &bhi[0]);
                    mma_f16(acc[mt][2 * np],     ahi[mt], &blo[0]);
                    mma_f16(acc[mt][2 * np + 1], ahi[mt], &bhi[2]);
                    mma_f16(acc[mt][2 * np + 1], ahi[mt], &blo[2]);
                }
            }
        }
        __syncthreads();
    }

    // ---- epilogue: write h (fp16) + alpha dot partials ----
    int r0 = rowBase + wm * MROWS + (lane >> 2);
    int colb = (lane & 3) * 2;
    float sp[MT][2], dp[MT][2];
    #pragma unroll
    for (int mt = 0; mt < MT; mt++) { sp[mt][0] = sp[mt][1] = dp[mt][0] = dp[mt][1] = 0.f; }

    #pragma unroll
    for (int mt = 0; mt < MT; mt++) {
        int rA = r0 + mt * 16;
        #pragma unroll
        for (int nt = 0; nt < 8; nt++) {
            int col = wn * 64 + nt * 8 + colb;
            float a0 = a_src[col], a1 = a_src[col + 1];
            float e0 = a_dst[col], e1 = a_dst[col + 1];
            sp[mt][0] = fmaf(acc[mt][nt][0], a0, fmaf(acc[mt][nt][1], a1, sp[mt][0]));
            dp[mt][0] = fmaf(acc[mt][nt][0], e0, fmaf(acc[mt][nt][1], e1, dp[mt][0]));
            sp[mt][1] = fmaf(acc[mt][nt][2], a0, fmaf(acc[mt][nt][3], a1, sp[mt][1]));
            dp[mt][1] = fmaf(acc[mt][nt][2], e0, fmaf(acc[mt][nt][3], e1, dp[mt][1]));
            if (rA < M)
                *reinterpret_cast<__half2*>(&g_h16[(size_t)rA * NDIM + col]) =
                    __floats2half2_rn(acc[mt][nt][0], acc[mt][nt][1]);
            if (rA + 8 < M)
                *reinterpret_cast<__half2*>(&g_h16[(size_t)(rA + 8) * NDIM + col]) =
                    __floats2half2_rn(acc[mt][nt][2], acc[mt][nt][3]);
        }
    }
    #pragma unroll
    for (int o = 1; o <= 2; o <<= 1) {
        #pragma unroll
        for (int mt = 0; mt < MT; mt++) {
            sp[mt][0] += __shfl_xor_sync(0xffffffffu, sp[mt][0], o);
            dp[mt][0] += __shfl_xor_sync(0xffffffffu, dp[mt][0], o);
            sp[mt][1] += __shfl_xor_sync(0xffffffffu, sp[mt][1], o);
            dp[mt][1] += __shfl_xor_sync(0xffffffffu, dp[mt][1], o);
        }
    }

    if constexpr (NDIM == 128) {
        float* sal = (float*)smem;   // reuse A region
        __syncthreads();
        if ((lane & 3) == 0) {
            int lr = wm * MROWS + (lane >> 2);
            #pragma unroll
            for (int mt = 0; mt < MT; mt++) {
                #pragma unroll
                for (int rh = 0; rh < 2; rh++) {
                    int row = lr + mt * 16 + rh * 8;
                    sal[row * 4 + wn * 2]     = (rh == 0) ? sp[mt][0] : sp[mt][1];
                    sal[row * 4 + wn * 2 + 1] = (rh == 0) ? dp[mt][0] : dp[mt][1];
                }
            }
        }
        __syncthreads();
        if (tid < 128) {
            int gr = rowBase + tid;
            if (gr < M) {
                g_as[gr] = sal[tid * 4] + sal[tid * 4 + 2];
                g_ad[gr] = sal[tid * 4 + 1] + sal[tid * 4 + 3];
            }
        }
    } else {
        if ((lane & 3) == 0) {
            if (r0 < M)     { g_as[r0] = sp[0][0];     g_ad[r0] = dp[0][0]; }
            if (r0 + 8 < M) { g_as[r0 + 8] = sp[0][1]; g_ad[r0 + 8] = dp[0][1]; }
        }
    }
}

// ---------------- aggregation with precomputed edge weights, fp16 h gather ----------------
template <int DO, bool TO_GX>
__global__ void aggregate_kernel(const float* __restrict__ bias,
                                 float* __restrict__ outp, int n) {
    constexpr int VEC = DO / 32;
    int node = (blockIdx.x * blockDim.x + threadIdx.x) >> 5;
    int lane = threadIdx.x & 31;
    if (node >= n) return;
    int s0 = g_off[node], s1 = g_off[node + 1];

    float acc[VEC];
    #pragma unroll
    for (int k = 0; k < VEC; k++) acc[k] = 0.f;
    float ssum = 0.f;

    const __half* hb = g_h16;
    int j = s0;
    #pragma unroll 1
    for (; j + 8 <= s1; j += 8) {
        int s[8];
        float w[8];
        #pragma unroll
        for (int q = 0; q < 8; q++) { s[q] = g_srcs[j + q]; w[q] = g_w[j + q]; }
        if constexpr (VEC == 4) {
            uint2 rr[8];
            #pragma unroll
            for (int q = 0; q < 8; q++)
                rr[q] = *reinterpret_cast<const uint2*>(&hb[(size_t)s[q] * DO + lane * 4]);
            #pragma unroll
            for (int q = 0; q < 8; q++) {
                ssum += w[q];
                float2 f0 = __half22float2(*reinterpret_cast<__half2*>(&rr[q].x));
                float2 f1 = __half22float2(*reinterpret_cast<__half2*>(&rr[q].y));
                acc[0] = fmaf(w[q], f0.x, acc[0]);
                acc[1] = fmaf(w[q], f0.y, acc[1]);
                acc[2] = fmaf(w[q], f1.x, acc[2]);
                acc[3] = fmaf(w[q], f1.y, acc[3]);
            }
        } else {
            uint32_t rr[8];
            #pragma unroll
            for (int q = 0; q < 8; q++)
                rr[q] = *reinterpret_cast<const uint32_t*>(&hb[(size_t)s[q] * DO + lane * 2]);
            #pragma unroll
            for (int q = 0; q < 8; q++) {
                ssum += w[q];
                float2 f0 = __half22float2(*reinterpret_cast<__half2*>(&rr[q]));
                acc[0] = fmaf(w[q], f0.x, acc[0]);
                acc[1] = fmaf(w[q], f0.y, acc[1]);
            }
        }
    }
    #pragma unroll 1
    for (; j < s1; ++j) {
        int s = g_srcs[j];
        float w = g_w[j];
        ssum += w;
        if constexpr (VEC == 4) {
            uint2 r = *reinterpret_cast<const uint2*>(&hb[(size_t)s * DO + lane * 4]);
            float2 f0 = __half22float2(*reinterpret_cast<__half2*>(&r.x));
            float2 f1 = __half22float2(*reinterpret_cast<__half2*>(&r.y));
            acc[0] = fmaf(w, f0.x, acc[0]);
            acc[1] = fmaf(w, f0.y, acc[1]);
            acc[2] = fmaf(w, f1.x, acc[2]);
            acc[3] = fmaf(w, f1.y, acc[3]);
        } else {
            uint32_t r = *reinterpret_cast<const uint32_t*>(&hb[(size_t)s * DO + lane * 2]);
            float2 f0 = __half22float2(*reinterpret_cast<__half2*>(&r));
            acc[0] = fmaf(w, f0.x, acc[0]);
            acc[1] = fmaf(w, f0.y, acc[1]);
        }
    }
    float inv = 1.f / ssum;
    #pragma unroll
    for (int k = 0; k < VEC; k++) {
        float o = fmaf(acc[k], inv, bias[lane * VEC + k]);
        acc[k] = o > 0.f ? o : 0.25f * o;
    }
    float* op = TO_GX ? &g_x[(size_t)node * DO + lane * VEC]
                      : &outp[(size_t)node * DO + lane * VEC];
    if constexpr (VEC == 4)
        *reinterpret_cast<float4*>(op) = make_float4(acc[0], acc[1], acc[2], acc[3]);
    else
        *reinterpret_cast<float2*>(op) = make_float2(acc[0], acc[1]);
}

// ---------------- launch ----------------
extern "C" void kernel_launch(void* const* d_in, const int* in_sizes, int n_in,
                              void* d_out, int out_size) {
    const float* data = (const float*)d_in[0];
    const int*   adj  = (const int*)d_in[1];
    const float* W1  = (const float*)d_in[2];
    const float* as1 = (const float*)d_in[3];
    const float* ad1 = (const float*)d_in[4];
    const float* b1  = (const float*)d_in[5];
    const float* W2  = (const float*)d_in[6];
    const float* as2 = (const float*)d_in[7];
    const float* ad2 = (const float*)d_in[8];
    const float* b2  = (const float*)d_in[9];
    const float* W3  = (const float*)d_in[10];
    const float* as3 = (const float*)d_in[11];
    const float* ad3 = (const float*)d_in[12];
    const float* b3  = (const float*)d_in[13];

    int Nn = in_sizes[0] / 512;
    int Ee = in_sizes[1] / 2;
    int Te = Ee + Nn;

    static cudaStream_t s2 = nullptr;
    static cudaEvent_t evFork = nullptr, evJoin = nullptr;
    static __half *pB1h, *pB1l, *pB2h, *pB2l, *pB3h, *pB3l;
    if (s2 == nullptr) {
        cudaStreamCreateWithFlags(&s2, cudaStreamNonBlocking);
        cudaEventCreateWithFlags(&evFork, cudaEventDisableTiming);
        cudaEventCreateWithFlags(&evJoin, cudaEventDisableTiming);
        void* p;
        cudaGetSymbolAddress(&p, g_B1h); pB1h = (__half*)p;
        cudaGetSymbolAddress(&p, g_B1l); pB1l = (__half*)p;
        cudaGetSymbolAddress(&p, g_B2h); pB2h = (__half*)p;
        cudaGetSymbolAddress(&p, g_B2l); pB2l = (__half*)p;
        cudaGetSymbolAddress(&p, g_B3h); pB3h = (__half*)p;
        cudaGetSymbolAddress(&p, g_B3l); pB3l = (__half*)p;
    }

    const int SM128 = 128 * 128 + 2 * 128 * 128 + 1024;  // 16K A + 32K B + pad
    const int SM64  = 128 * 128 + 2 * 64 * 128 + 1024;   // 16K A + 16K B + pad
    cudaFuncSetAttribute(mma_gemm_kernel<128>,
                         cudaFuncAttributeMaxDynamicSharedMemorySize, SM128);
    cudaFuncSetAttribute(mma_gemm_kernel<64>,
                         cudaFuncAttributeMaxDynamicSharedMemorySize, SM64);

    const int T = 256;
    int warpGrid = (Nn * 32 + T - 1) / T;
    int edgeGrid = (Te + T - 1) / T;
    const int* dst32 = adj + Ee;
    const int* dst64 = adj + 2 * (size_t)Ee;
    int gBlocks = (Nn + 127) / 128;
    int nb = (Nn + SCAN_BS - 1) / SCAN_BS;

    cudaEventRecord(evFork, 0);
    cudaStreamWaitEvent(s2, evFork, 0);
    detect_kernel<<<1, 32, 0, s2>>>(adj);
    init_deg_kernel<<<(Nn + T - 1) / T, T, 0, s2>>>(Nn);

    wsplit_kernel<<<(512 * 128 + T - 1) / T, T>>>(W1, pB1h, pB1l, 512, 128);
    mma_gemm_kernel<128><<<gBlocks, 256, SM128>>>(data, 0, Nn, 512, pB1h, pB1l, as1, ad1);

    count2_kernel<<<(Ee + T - 1) / T, T, 0, s2>>>(dst32, dst64, Ee);
    blockscan_kernel<<<nb, SCAN_BS, 0, s2>>>(Nn);
    bsumscan_kernel<<<1, 512, 0, s2>>>(nb, Nn);
    addoff_kernel<<<(Nn + T - 1) / T, T, 0, s2>>>(Nn);
    scatter2_kernel<<<(Ee + Nn + T - 1) / T, T, 0, s2>>>(adj, dst32, dst64, Ee, Nn);
    wsplit_kernel<<<(128 * 128 + T - 1) / T, T, 0, s2>>>(W2, pB2h, pB2l, 128, 128);
    wsplit_kernel<<<(128 * 64 + T - 1) / T, T, 0, s2>>>(W3, pB3h, pB3l, 128, 64);
    cudaEventRecord(evJoin, s2);

    cudaStreamWaitEvent(0, evJoin, 0);
    edgew_kernel<<<edgeGrid, T>>>(Te);
    aggregate_kernel<128, true><<<warpGrid, T>>>(b1, nullptr, Nn);

    mma_gemm_kernel<128><<<gBlocks, 256, SM128>>>(nullptr, 1, Nn, 128, pB2h, pB2l, as2, ad2);
    edgew_kernel<<<edgeGrid, T>>>(Te);
    aggregate_kernel<128, true><<<warpGrid, T>>>(b2, nullptr, Nn);

    mma_gemm_kernel<64><<<gBlocks, 256, SM64>>>(nullptr, 1, Nn, 128, pB3h, pB3l, as3, ad3);
    edgew_kernel<<<edgeGrid, T>>>(Te);
    aggregate_kernel<64, false><<<warpGrid, T>>>(b3, (float*)d_out, Nn);
}

// round 15
// speedup vs baseline: 1.1665x; 1.0291x over previous
#include <cuda_runtime.h>
#include <cuda_fp16.h>
#include <cstdint>

#define MAXN 100000
#define MAXE 1600000
#define MAXT (MAXE + MAXN)

// ---------------- scratch (static device globals; no runtime allocation) ----------------
__device__ __align__(16) __half g_h16[(size_t)MAXN * 128]; // per-layer h = x @ W (fp16)
__device__ __align__(16) __half g_x16[(size_t)MAXN * 128]; // activations between layers (fp16)
__device__ float g_as[MAXN];
__device__ float g_ad[MAXN];
__device__ int   g_deg[MAXN];
__device__ int   g_off[MAXN + 1];
__device__ int   g_cur[MAXN];
__device__ int   g_srcs[MAXT];
__device__ int   g_dsts[MAXT];
__device__ float g_w[MAXT];
__device__ int   g_is64;
__device__ int   g_bsum[512];
// per-layer W^T fp16 hi/lo splits
__device__ __align__(8) __half g_B1h[128 * 512], g_B1l[128 * 512];
__device__ __align__(8) __half g_B2h[128 * 128], g_B2l[128 * 128];
__device__ __align__(8) __half g_B3h[64 * 128],  g_B3l[64 * 128];

// ================= helpers =================
__device__ __forceinline__ uint32_t smem_u32(const void* p) {
    uint32_t a;
    asm("{ .reg .u64 t; cvta.to.shared.u64 t, %1; cvt.u32.u64 %0, t; }" : "=r"(a) : "l"(p));
    return a;
}
__device__ __forceinline__ uint32_t pack_f16(float a, float b) {  // a -> low, b -> high
    uint32_t r;
    asm("cvt.rn.f16x2.f32 %0, %1, %2;" : "=r"(r) : "f"(b), "f"(a));
    return r;
}
__device__ __forceinline__ void ldm_x4(uint32_t* r, uint32_t addr) {
    asm volatile("ldmatrix.sync.aligned.m8n8.x4.shared.b16 {%0,%1,%2,%3}, [%4];"
                 : "=r"(r[0]), "=r"(r[1]), "=r"(r[2]), "=r"(r[3]) : "r"(addr));
}
__device__ __forceinline__ void mma_f16(float* c, const uint32_t* a, const uint32_t* b) {
    asm volatile(
        "mma.sync.aligned.m16n8k16.row.col.f32.f16.f16.f32 "
        "{%0,%1,%2,%3},{%4,%5,%6,%7},{%8,%9},{%0,%1,%2,%3};"
        : "+f"(c[0]), "+f"(c[1]), "+f"(c[2]), "+f"(c[3])
        : "r"(a[0]), "r"(a[1]), "r"(a[2]), "r"(a[3]), "r"(b[0]), "r"(b[1]));
}
__device__ __forceinline__ void sts64(uint32_t addr, uint32_t a, uint32_t b) {
    asm volatile("st.shared.v2.u32 [%0], {%1, %2};" :: "r"(addr), "r"(a), "r"(b) : "memory");
}
__device__ __forceinline__ void cp_async8(uint32_t saddr, const void* gptr) {
    asm volatile("cp.async.ca.shared.global [%0], [%1], 8;"
                 :: "r"(saddr), "l"(gptr) : "memory");
}
__device__ __forceinline__ void cp_async16(uint32_t saddr, const void* gptr) {
    asm volatile("cp.async.cg.shared.global [%0], [%1], 16;"
                 :: "r"(saddr), "l"(gptr) : "memory");
}
__device__ __forceinline__ void cp_async_commit_wait() {
    asm volatile("cp.async.commit_group;" ::: "memory");
    asm volatile("cp.async.wait_group 0;" ::: "memory");
}
__device__ __forceinline__ float leaky02(float v) { return v > 0.f ? v : 0.2f * v; }

// ---------------- adjacency dtype detection ----------------
__global__ void detect_kernel(const int* __restrict__ w) {
    if (threadIdx.x == 0) {
        int all0 = 1;
        #pragma unroll 1
        for (int i = 0; i < 64; i++)
            if (w[2 * i + 1] != 0) { all0 = 0; break; }
        g_is64 = all0;
    }
}

// ---------------- CSR build ----------------
__global__ void init_deg_kernel(int n) {
    int i = blockIdx.x * blockDim.x + threadIdx.x;
    if (i < n) g_deg[i] = 1;  // self-loop
}

__global__ void count2_kernel(const int* __restrict__ dst32,
                              const int* __restrict__ dst64, int e) {
    int i = blockIdx.x * blockDim.x + threadIdx.x;
    if (i >= e) return;
    int is64 = g_is64;
    int d = is64 ? dst64[2 * i] : dst32[i];
    atomicAdd(&g_deg[d], 1);
}

#define SCAN_BS 512
__global__ void blockscan_kernel(int n) {
    __shared__ int sh[SCAN_BS];
    int t = threadIdx.x;
    int i = blockIdx.x * SCAN_BS + t;
    int v = (i < n) ? g_deg[i] : 0;
    sh[t] = v;
    __syncthreads();
    #pragma unroll
    for (int d = 1; d < SCAN_BS; d <<= 1) {
        int x = (t >= d) ? sh[t - d] : 0;
        __syncthreads();
        sh[t] += x;
        __syncthreads();
    }
    if (i < n) g_off[i] = sh[t] - v;
    if (t == SCAN_BS - 1) g_bsum[blockIdx.x] = sh[t];
}

__global__ void bsumscan_kernel(int nb, int n) {
    __shared__ int sh[512];
    int t = threadIdx.x;
    int v = (t < nb) ? g_bsum[t] : 0;
    sh[t] = v;
    __syncthreads();
    #pragma unroll
    for (int d = 1; d < 512; d <<= 1) {
        int x = (t >= d) ? sh[t - d] : 0;
        __syncthreads();
        sh[t] += x;
        __syncthreads();
    }
    if (t < nb) g_bsum[t] = sh[t] - v;
    if (t == 511) g_off[n] = sh[511];
}

__global__ void addoff_kernel(int n) {
    int i = blockIdx.x * blockDim.x + threadIdx.x;
    if (i < n) {
        int o = g_off[i] + g_bsum[i >> 9];
        g_off[i] = o;
        g_cur[i] = o;
    }
}

__global__ void scatter2_kernel(const int* __restrict__ src,
                                const int* __restrict__ dst32,
                                const int* __restrict__ dst64, int e, int n) {
    int i = blockIdx.x * blockDim.x + threadIdx.x;
    int is64 = g_is64;
    if (i < e) {
        int d = is64 ? dst64[2 * i] : dst32[i];
        int s = is64 ? src[2 * i] : src[i];
        int p = atomicAdd(&g_cur[d], 1);
        g_srcs[p] = s;
        g_dsts[p] = d;
    } else if (i < e + n) {
        int v = i - e;
        int p = atomicAdd(&g_cur[v], 1);
        g_srcs[p] = v;
        g_dsts[p] = v;
    }
}

// ---------------- W transpose + fp16 hi/lo split ----------------
__global__ void wsplit_kernel(const float* __restrict__ W,
                              __half* __restrict__ Bh,
                              __half* __restrict__ Bl, int K, int Nd) {
    int i = blockIdx.x * blockDim.x + threadIdx.x;
    if (i >= K * Nd) return;
    int k = i / Nd, nn = i % Nd;
    float x = W[i];
    __half h = __float2half_rn(x);
    Bh[(size_t)nn * K + k] = h;
    Bl[(size_t)nn * K + k] = __float2half_rn(x - __half2float(h));
}

// ---------------- edge weights ----------------
__global__ void edgew_kernel(int t) {
    int i = blockIdx.x * blockDim.x + threadIdx.x;
    if (i >= t) return;
    int s = g_srcs[i];
    int d = g_dsts[i];
    g_w[i] = __expf(leaky02(g_as[s] + g_ad[d]));
}

// ---------------- mma.sync 2-term fp16-split GEMM + fused alpha dots ----------------
// A16=false: A fp32 (layer 1) via register prefetch + pack.
// A16=true:  A fp16 (g_x16) staged directly via cp.async 16B.
template <int NDIM, bool A16>
__global__ void __launch_bounds__(256, 2)
mma_gemm_kernel(const float* __restrict__ Af32, const __half* __restrict__ Ah16,
                int M, int K,
                const __half* __restrict__ Bhi,
                const __half* __restrict__ Blo,
                const float* __restrict__ a_src, const float* __restrict__ a_dst) {
    constexpr int ABYTES = 128 * 128;
    constexpr int BBYTES = NDIM * 128;
    constexpr int BP = NDIM / 16;
    constexpr int MT = (NDIM == 128) ? 2 : 1;
    constexpr int MROWS = MT * 16;
    extern __shared__ char smraw[];
    char* smem = (char*)(((uintptr_t)smraw + 1023) & ~(uintptr_t)1023);
    uint32_t aHiB = smem_u32(smem);
    uint32_t bHiB = aHiB + ABYTES;
    uint32_t bLoB = bHiB + BBYTES;

    const int tid = threadIdx.x, wid = tid >> 5, lane = tid & 31;
    const int rowBase = blockIdx.x * 128;
    const int wm = (NDIM == 128) ? (wid & 3) : wid;
    const int wn = (NDIM == 128) ? (wid >> 2) : 0;

    float acc[MT][8][4];
    #pragma unroll
    for (int mt = 0; mt < MT; mt++)
        #pragma unroll
        for (int nt = 0; nt < 8; nt++)
            #pragma unroll
            for (int q = 0; q < 4; q++) acc[mt][nt][q] = 0.f;

    const int aRow = wm * MROWS + (lane & 7) + ((lane >> 3) & 1) * 8;
    const uint32_t aRowOff = (uint32_t)aRow * 128;
    const uint32_t aSwz = (uint32_t)(lane & 7) << 4;
    const uint32_t aHalf = ((lane >> 4) & 1) * 16;
    const uint32_t bRow4 = (uint32_t)((lane & 7) | ((lane >> 4) << 3));
    const uint32_t bRowOff4 = (uint32_t)(wn * 64 + bRow4) * 128;
    const uint32_t bSwz4 = (uint32_t)(lane & 7) << 4;
    const uint32_t bHalf4 = ((lane >> 3) & 1) * 16;

    const int sr = tid >> 4;            // 0..15 (fp32 A staging + B staging)
    const int cg = (tid & 15) * 4;      // fp32 col group / half col*? (B: halves)
    const uint32_t stCol = (uint32_t)(cg * 2);
    // fp16 A staging (cp.async16): row = p*32 + (tid>>3), seg = tid&7 (16B each)
    const int a16row = tid >> 3;        // 0..31
    const uint32_t a16seg = (uint32_t)(tid & 7) * 16;

    const int nChunks = K >> 6;

    float4 pref[8];
    if constexpr (!A16) {
        #pragma unroll
        for (int p = 0; p < 8; p++) {
            int gr = rowBase + p * 16 + sr;
            pref[p] = make_float4(0.f, 0.f, 0.f, 0.f);
            if (gr < M)
                pref[p] = *reinterpret_cast<const float4*>(&Af32[(size_t)gr * K + cg]);
        }
    }

    for (int c = 0; c < nChunks; c++) {
        const int k0 = c << 6;
        // ---- B staging via cp.async ----
        #pragma unroll
        for (int p = 0; p < BP; p++) {
            int r = p * 16 + sr;
            uint32_t off = (uint32_t)r * 128 + (stCol ^ ((uint32_t)(r & 7) << 4));
            cp_async8(bHiB + off, &Bhi[(size_t)r * K + k0 + cg]);
            cp_async8(bLoB + off, &Blo[(size_t)r * K + k0 + cg]);
        }
        // ---- A staging ----
        if constexpr (A16) {
            #pragma unroll
            for (int p = 0; p < 4; p++) {
                int r = p * 32 + a16row;
                int gr = rowBase + r;
                const __half* src = (gr < M)
                    ? &Ah16[(size_t)gr * K + k0 + (tid & 7) * 8]
                    : Ah16;   // safe dummy read; rows >= M never stored
                uint32_t off = (uint32_t)r * 128 + (a16seg ^ ((uint32_t)(r & 7) << 4));
                cp_async16(aHiB + off, src);
            }
        } else {
            #pragma unroll
            for (int p = 0; p < 8; p++) {
                int r = p * 16 + sr;
                float4 v = pref[p];
                uint32_t off = (uint32_t)r * 128 + (stCol ^ ((uint32_t)(r & 7) << 4));
                sts64(aHiB + off, pack_f16(v.x, v.y), pack_f16(v.z, v.w));
            }
        }
        cp_async_commit_wait();
        __syncthreads();

        // ---- prefetch fp32 A chunk c+1 (overlaps with MMA) ----
        if constexpr (!A16) {
            if (c + 1 < nChunks) {
                const int k1 = (c + 1) << 6;
                #pragma unroll
                for (int p = 0; p < 8; p++) {
                    int gr = rowBase + p * 16 + sr;
                    pref[p] = make_float4(0.f, 0.f, 0.f, 0.f);
                    if (gr < M)
                        pref[p] = *reinterpret_cast<const float4*>(&Af32[(size_t)gr * K + k1 + cg]);
                }
            }
        }

        // ---- compute: 2-term (Ah*Bh + Ah*Bl) ----
        #pragma unroll
        for (int kt = 0; kt < 4; kt++) {
            uint32_t kc = (uint32_t)kt * 32;
            uint32_t aoff = aRowOff + ((kc + aHalf) ^ aSwz);
            uint32_t ahi[MT][4];
            #pragma unroll
            for (int mt = 0; mt < MT; mt++)
                ldm_x4(ahi[mt], aHiB + aoff + (uint32_t)mt * 2048);
            uint32_t bcol = (kc + bHalf4) ^ bSwz4;
            #pragma unroll
            for (int np = 0; np < 4; np++) {
                uint32_t boff = bRowOff4 + (uint32_t)np * 2048 + bcol;
                uint32_t bhi[4], blo[4];
                ldm_x4(bhi, bHiB + boff);
                ldm_x4(blo, bLoB + boff);
                #pragma unroll
                for (int mt = 0; mt < MT; mt++) {
                    mma_f16(acc[mt][2 * np],     ahi[mt], &bhi[0]);
                    mma_f16(acc[mt][2 * np],     ahi[mt], &blo[0]);
                    mma_f16(acc[mt][2 * np + 1], ahi[mt], &bhi[2]);
                    mma_f16(acc[mt][2 * np + 1], ahi[mt], &blo[2]);
                }
            }
        }
        __syncthreads();
    }

    // ---- epilogue: write h (fp16) + alpha dot partials ----
    int r0 = rowBase + wm * MROWS + (lane >> 2);
    int colb = (lane & 3) * 2;
    float sp[MT][2], dp[MT][2];
    #pragma unroll
    for (int mt = 0; mt < MT; mt++) { sp[mt][0] = sp[mt][1] = dp[mt][0] = dp[mt][1] = 0.f; }

    #pragma unroll
    for (int mt = 0; mt < MT; mt++) {
        int rA = r0 + mt * 16;
        #pragma unroll
        for (int nt = 0; nt < 8; nt++) {
            int col = wn * 64 + nt * 8 + colb;
            float a0 = a_src[col], a1 = a_src[col + 1];
            float e0 = a_dst[col], e1 = a_dst[col + 1];
            sp[mt][0] = fmaf(acc[mt][nt][0], a0, fmaf(acc[mt][nt][1], a1, sp[mt][0]));
            dp[mt][0] = fmaf(acc[mt][nt][0], e0, fmaf(acc[mt][nt][1], e1, dp[mt][0]));
            sp[mt][1] = fmaf(acc[mt][nt][2], a0, fmaf(acc[mt][nt][3], a1, sp[mt][1]));
            dp[mt][1] = fmaf(acc[mt][nt][2], e0, fmaf(acc[mt][nt][3], e1, dp[mt][1]));
            if (rA < M)
                *reinterpret_cast<__half2*>(&g_h16[(size_t)rA * NDIM + col]) =
                    __floats2half2_rn(acc[mt][nt][0], acc[mt][nt][1]);
            if (rA + 8 < M)
                *reinterpret_cast<__half2*>(&g_h16[(size_t)(rA + 8) * NDIM + col]) =
                    __floats2half2_rn(acc[mt][nt][2], acc[mt][nt][3]);
        }
    }
    #pragma unroll
    for (int o = 1; o <= 2; o <<= 1) {
        #pragma unroll
        for (int mt = 0; mt < MT; mt++) {
            sp[mt][0] += __shfl_xor_sync(0xffffffffu, sp[mt][0], o);
            dp[mt][0] += __shfl_xor_sync(0xffffffffu, dp[mt][0], o);
            sp[mt][1] += __shfl_xor_sync(0xffffffffu, sp[mt][1], o);
            dp[mt][1] += __shfl_xor_sync(0xffffffffu, dp[mt][1], o);
        }
    }

    if constexpr (NDIM == 128) {
        float* sal = (float*)smem;   // reuse A region
        __syncthreads();
        if ((lane & 3) == 0) {
            int lr = wm * MROWS + (lane >> 2);
            #pragma unroll
            for (int mt = 0; mt < MT; mt++) {
                #pragma unroll
                for (int rh = 0; rh < 2; rh++) {
                    int row = lr + mt * 16 + rh * 8;
                    sal[row * 4 + wn * 2]     = (rh == 0) ? sp[mt][0] : sp[mt][1];
                    sal[row * 4 + wn * 2 + 1] = (rh == 0) ? dp[mt][0] : dp[mt][1];
                }
            }
        }
        __syncthreads();
        if (tid < 128) {
            int gr = rowBase + tid;
            if (gr < M) {
                g_as[gr] = sal[tid * 4] + sal[tid * 4 + 2];
                g_ad[gr] = sal[tid * 4 + 1] + sal[tid * 4 + 3];
            }
        }
    } else {
        if ((lane & 3) == 0) {
            if (r0 < M)     { g_as[r0] = sp[0][0];     g_ad[r0] = dp[0][0]; }
            if (r0 + 8 < M) { g_as[r0 + 8] = sp[0][1]; g_ad[r0 + 8] = dp[0][1]; }
        }
    }
}

// ---------------- aggregation with precomputed edge weights, fp16 h gather ----------------
// TO_GX: write fp16 g_x16 for the next GEMM; else fp32 to d_out.
template <int DO, bool TO_GX>
__global__ void aggregate_kernel(const float* __restrict__ bias,
                                 float* __restrict__ outp, int n) {
    constexpr int VEC = DO / 32;
    int node = (blockIdx.x * blockDim.x + threadIdx.x) >> 5;
    int lane = threadIdx.x & 31;
    if (node >= n) return;
    int s0 = g_off[node], s1 = g_off[node + 1];

    float acc[VEC];
    #pragma unroll
    for (int k = 0; k < VEC; k++) acc[k] = 0.f;
    float ssum = 0.f;

    const __half* hb = g_h16;
    int j = s0;
    #pragma unroll 1
    for (; j + 8 <= s1; j += 8) {
        int s[8];
        float w[8];
        #pragma unroll
        for (int q = 0; q < 8; q++) { s[q] = g_srcs[j + q]; w[q] = g_w[j + q]; }
        if constexpr (VEC == 4) {
            uint2 rr[8];
            #pragma unroll
            for (int q = 0; q < 8; q++)
                rr[q] = *reinterpret_cast<const uint2*>(&hb[(size_t)s[q] * DO + lane * 4]);
            #pragma unroll
            for (int q = 0; q < 8; q++) {
                ssum += w[q];
                float2 f0 = __half22float2(*reinterpret_cast<__half2*>(&rr[q].x));
                float2 f1 = __half22float2(*reinterpret_cast<__half2*>(&rr[q].y));
                acc[0] = fmaf(w[q], f0.x, acc[0]);
                acc[1] = fmaf(w[q], f0.y, acc[1]);
                acc[2] = fmaf(w[q], f1.x, acc[2]);
                acc[3] = fmaf(w[q], f1.y, acc[3]);
            }
        } else {
            uint32_t rr[8];
            #pragma unroll
            for (int q = 0; q < 8; q++)
                rr[q] = *reinterpret_cast<const uint32_t*>(&hb[(size_t)s[q] * DO + lane * 2]);
            #pragma unroll
            for (int q = 0; q < 8; q++) {
                ssum += w[q];
                float2 f0 = __half22float2(*reinterpret_cast<__half2*>(&rr[q]));
                acc[0] = fmaf(w[q], f0.x, acc[0]);
                acc[1] = fmaf(w[q], f0.y, acc[1]);
            }
        }
    }
    #pragma unroll 1
    for (; j < s1; ++j) {
        int s = g_srcs[j];
        float w = g_w[j];
        ssum += w;
        if constexpr (VEC == 4) {
            uint2 r = *reinterpret_cast<const uint2*>(&hb[(size_t)s * DO + lane * 4]);
            float2 f0 = __half22float2(*reinterpret_cast<__half2*>(&r.x));
            float2 f1 = __half22float2(*reinterpret_cast<__half2*>(&r.y));
            acc[0] = fmaf(w, f0.x, acc[0]);
            acc[1] = fmaf(w, f0.y, acc[1]);
            acc[2] = fmaf(w, f1.x, acc[2]);
            acc[3] = fmaf(w, f1.y, acc[3]);
        } else {
            uint32_t r = *reinterpret_cast<const uint32_t*>(&hb[(size_t)s * DO + lane * 2]);
            float2 f0 = __half22float2(*reinterpret_cast<__half2*>(&r));
            acc[0] = fmaf(w, f0.x, acc[0]);
            acc[1] = fmaf(w, f0.y, acc[1]);
        }
    }
    float inv = 1.f / ssum;
    #pragma unroll
    for (int k = 0; k < VEC; k++) {
        float o = fmaf(acc[k], inv, bias[lane * VEC + k]);
        acc[k] = o > 0.f ? o : 0.25f * o;
    }
    if constexpr (TO_GX) {
        __half* xp = &g_x16[(size_t)node * DO + lane * VEC];
        if constexpr (VEC == 4) {
            uint2 v;
            *reinterpret_cast<__half2*>(&v.x) = __floats2half2_rn(acc[0], acc[1]);
            *reinterpret_cast<__half2*>(&v.y) = __floats2half2_rn(acc[2], acc[3]);
            *reinterpret_cast<uint2*>(xp) = v;
        } else {
            *reinterpret_cast<__half2*>(xp) = __floats2half2_rn(acc[0], acc[1]);
        }
    } else {
        float* op = &outp[(size_t)node * DO + lane * VEC];
        if constexpr (VEC == 4)
            *reinterpret_cast<float4*>(op) = make_float4(acc[0], acc[1], acc[2], acc[3]);
        else
            *reinterpret_cast<float2*>(op) = make_float2(acc[0], acc[1]);
    }
}

// ---------------- launch ----------------
extern "C" void kernel_launch(void* const* d_in, const int* in_sizes, int n_in,
                              void* d_out, int out_size) {
    const float* data = (const float*)d_in[0];
    const int*   adj  = (const int*)d_in[1];
    const float* W1  = (const float*)d_in[2];
    const float* as1 = (const float*)d_in[3];
    const float* ad1 = (const float*)d_in[4];
    const float* b1  = (const float*)d_in[5];
    const float* W2  = (const float*)d_in[6];
    const float* as2 = (const float*)d_in[7];
    const float* ad2 = (const float*)d_in[8];
    const float* b2  = (const float*)d_in[9];
    const float* W3  = (const float*)d_in[10];
    const float* as3 = (const float*)d_in[11];
    const float* ad3 = (const float*)d_in[12];
    const float* b3  = (const float*)d_in[13];

    int Nn = in_sizes[0] / 512;
    int Ee = in_sizes[1] / 2;
    int Te = Ee + Nn;

    static cudaStream_t s2 = nullptr;
    static cudaEvent_t evFork = nullptr, evJoin = nullptr;
    static __half *pB1h, *pB1l, *pB2h, *pB2l, *pB3h, *pB3l, *pX16;
    if (s2 == nullptr) {
        cudaStreamCreateWithFlags(&s2, cudaStreamNonBlocking);
        cudaEventCreateWithFlags(&evFork, cudaEventDisableTiming);
        cudaEventCreateWithFlags(&evJoin, cudaEventDisableTiming);
        void* p;
        cudaGetSymbolAddress(&p, g_B1h); pB1h = (__half*)p;
        cudaGetSymbolAddress(&p, g_B1l); pB1l = (__half*)p;
        cudaGetSymbolAddress(&p, g_B2h); pB2h = (__half*)p;
        cudaGetSymbolAddress(&p, g_B2l); pB2l = (__half*)p;
        cudaGetSymbolAddress(&p, g_B3h); pB3h = (__half*)p;
        cudaGetSymbolAddress(&p, g_B3l); pB3l = (__half*)p;
        cudaGetSymbolAddress(&p, g_x16); pX16 = (__half*)p;
    }

    const int SM128 = 128 * 128 + 2 * 128 * 128 + 1024;  // 16K A + 32K B + pad
    const int SM64  = 128 * 128 + 2 * 64 * 128 + 1024;   // 16K A + 16K B + pad
    cudaFuncSetAttribute((const void*)mma_gemm_kernel<128, false>,
                         cudaFuncAttributeMaxDynamicSharedMemorySize, SM128);
    cudaFuncSetAttribute((const void*)mma_gemm_kernel<128, true>,
                         cudaFuncAttributeMaxDynamicSharedMemorySize, SM128);
    cudaFuncSetAttribute((const void*)mma_gemm_kernel<64, true>,
                         cudaFuncAttributeMaxDynamicSharedMemorySize, SM64);

    const int T = 256;
    int warpGrid = (Nn * 32 + T - 1) / T;
    int edgeGrid = (Te + T - 1) / T;
    const int* dst32 = adj + Ee;
    const int* dst64 = adj + 2 * (size_t)Ee;
    int gBlocks = (Nn + 127) / 128;
    int nb = (Nn + SCAN_BS - 1) / SCAN_BS;

    cudaEventRecord(evFork, 0);
    cudaStreamWaitEvent(s2, evFork, 0);
    detect_kernel<<<1, 32, 0, s2>>>(adj);
    init_deg_kernel<<<(Nn + T - 1) / T, T, 0, s2>>>(Nn);

    wsplit_kernel<<<(512 * 128 + T - 1) / T, T>>>(W1, pB1h, pB1l, 512, 128);
    mma_gemm_kernel<128, false><<<gBlocks, 256, SM128>>>(
        data, nullptr, Nn, 512, pB1h, pB1l, as1, ad1);

    count2_kernel<<<(Ee + T - 1) / T, T, 0, s2>>>(dst32, dst64, Ee);
    blockscan_kernel<<<nb, SCAN_BS, 0, s2>>>(Nn);
    bsumscan_kernel<<<1, 512, 0, s2>>>(nb, Nn);
    addoff_kernel<<<(Nn + T - 1) / T, T, 0, s2>>>(Nn);
    scatter2_kernel<<<(Ee + Nn + T - 1) / T, T, 0, s2>>>(adj, dst32, dst64, Ee, Nn);
    wsplit_kernel<<<(128 * 128 + T - 1) / T, T, 0, s2>>>(W2, pB2h, pB2l, 128, 128);
    wsplit_kernel<<<(128 * 64 + T - 1) / T, T, 0, s2>>>(W3, pB3h, pB3l, 128, 64);
    cudaEventRecord(evJoin, s2);

    cudaStreamWaitEvent(0, evJoin, 0);
    edgew_kernel<<<edgeGrid, T>>>(Te);
    aggregate_kernel<128, true><<<warpGrid, T>>>(b1, nullptr, Nn);

    mma_gemm_kernel<128, true><<<gBlocks, 256, SM128>>>(
        nullptr, pX16, Nn, 128, pB2h, pB2l, as2, ad2);
    edgew_kernel<<<edgeGrid, T>>>(Te);
    aggregate_kernel<128, true><<<warpGrid, T>>>(b2, nullptr, Nn);

    mma_gemm_kernel<64, true><<<gBlocks, 256, SM64>>>(
        nullptr, pX16, Nn, 128, pB3h, pB3l, as3, ad3);
    edgew_kernel<<<edgeGrid, T>>>(Te);
    aggregate_kernel<64, false><<<warpGrid, T>>>(b3, (float*)d_out, Nn);
}

// round 16
// speedup vs baseline: 1.3303x; 1.1404x over previous
#include <cuda_runtime.h>
#include <cuda_fp16.h>
#include <cstdint>

#define MAXN 100000
#define MAXE 1600000
#define MAXT (MAXE + MAXN)

// ---------------- scratch (static device globals; no runtime allocation) ----------------
__device__ __align__(16) __half g_h16[(size_t)MAXN * 128]; // per-layer h = x @ W (fp16)
__device__ __align__(16) __half g_x16[(size_t)MAXN * 128]; // activations between layers (fp16)
__device__ float g_as[MAXN];
__device__ float g_ad[MAXN];
__device__ int   g_deg[MAXN];
__device__ int   g_off[MAXN + 1];
__device__ int   g_cur[MAXN];
__device__ int   g_srcs[MAXT];
__device__ int   g_dsts[MAXT];
__device__ float g_w[MAXT];
__device__ int   g_is64;
__device__ int   g_bsum[512];
// per-layer W^T fp16
__device__ __align__(8) __half g_B1h[128 * 512];
__device__ __align__(8) __half g_B2h[128 * 128];
__device__ __align__(8) __half g_B3h[64 * 128];

// ================= helpers =================
__device__ __forceinline__ uint32_t smem_u32(const void* p) {
    uint32_t a;
    asm("{ .reg .u64 t; cvta.to.shared.u64 t, %1; cvt.u32.u64 %0, t; }" : "=r"(a) : "l"(p));
    return a;
}
__device__ __forceinline__ uint32_t pack_f16(float a, float b) {  // a -> low, b -> high
    uint32_t r;
    asm("cvt.rn.f16x2.f32 %0, %1, %2;" : "=r"(r) : "f"(b), "f"(a));
    return r;
}
__device__ __forceinline__ void ldm_x4(uint32_t* r, uint32_t addr) {
    asm volatile("ldmatrix.sync.aligned.m8n8.x4.shared.b16 {%0,%1,%2,%3}, [%4];"
                 : "=r"(r[0]), "=r"(r[1]), "=r"(r[2]), "=r"(r[3]) : "r"(addr));
}
__device__ __forceinline__ void mma_f16(float* c, const uint32_t* a, const uint32_t* b) {
    asm volatile(
        "mma.sync.aligned.m16n8k16.row.col.f32.f16.f16.f32 "
        "{%0,%1,%2,%3},{%4,%5,%6,%7},{%8,%9},{%0,%1,%2,%3};"
        : "+f"(c[0]), "+f"(c[1]), "+f"(c[2]), "+f"(c[3])
        : "r"(a[0]), "r"(a[1]), "r"(a[2]), "r"(a[3]), "r"(b[0]), "r"(b[1]));
}
__device__ __forceinline__ void sts64(uint32_t addr, uint32_t a, uint32_t b) {
    asm volatile("st.shared.v2.u32 [%0], {%1, %2};" :: "r"(addr), "r"(a), "r"(b) : "memory");
}
__device__ __forceinline__ void cp_async8(uint32_t saddr, const void* gptr) {
    asm volatile("cp.async.ca.shared.global [%0], [%1], 8;"
                 :: "r"(saddr), "l"(gptr) : "memory");
}
__device__ __forceinline__ void cp_async16(uint32_t saddr, const void* gptr) {
    asm volatile("cp.async.cg.shared.global [%0], [%1], 16;"
                 :: "r"(saddr), "l"(gptr) : "memory");
}
__device__ __forceinline__ void cp_async_commit_wait() {
    asm volatile("cp.async.commit_group;" ::: "memory");
    asm volatile("cp.async.wait_group 0;" ::: "memory");
}
__device__ __forceinline__ float leaky02(float v) { return v > 0.f ? v : 0.2f * v; }

// ---------------- adjacency dtype detection ----------------
__global__ void detect_kernel(const int* __restrict__ w) {
    if (threadIdx.x == 0) {
        int all0 = 1;
        #pragma unroll 1
        for (int i = 0; i < 64; i++)
            if (w[2 * i + 1] != 0) { all0 = 0; break; }
        g_is64 = all0;
    }
}

// ---------------- CSR build ----------------
__global__ void init_deg_kernel(int n) {
    int i = blockIdx.x * blockDim.x + threadIdx.x;
    if (i < n) g_deg[i] = 1;  // self-loop
}

__global__ void count2_kernel(const int* __restrict__ dst32,
                              const int* __restrict__ dst64, int e) {
    int i = blockIdx.x * blockDim.x + threadIdx.x;
    if (i >= e) return;
    int is64 = g_is64;
    int d = is64 ? dst64[2 * i] : dst32[i];
    atomicAdd(&g_deg[d], 1);
}

#define SCAN_BS 512
__global__ void blockscan_kernel(int n) {
    __shared__ int sh[SCAN_BS];
    int t = threadIdx.x;
    int i = blockIdx.x * SCAN_BS + t;
    int v = (i < n) ? g_deg[i] : 0;
    sh[t] = v;
    __syncthreads();
    #pragma unroll
    for (int d = 1; d < SCAN_BS; d <<= 1) {
        int x = (t >= d) ? sh[t - d] : 0;
        __syncthreads();
        sh[t] += x;
        __syncthreads();
    }
    if (i < n) g_off[i] = sh[t] - v;
    if (t == SCAN_BS - 1) g_bsum[blockIdx.x] = sh[t];
}

__global__ void bsumscan_kernel(int nb, int n) {
    __shared__ int sh[512];
    int t = threadIdx.x;
    int v = (t < nb) ? g_bsum[t] : 0;
    sh[t] = v;
    __syncthreads();
    #pragma unroll
    for (int d = 1; d < 512; d <<= 1) {
        int x = (t >= d) ? sh[t - d] : 0;
        __syncthreads();
        sh[t] += x;
        __syncthreads();
    }
    if (t < nb) g_bsum[t] = sh[t] - v;
    if (t == 511) g_off[n] = sh[511];
}

__global__ void addoff_kernel(int n) {
    int i = blockIdx.x * blockDim.x + threadIdx.x;
    if (i < n) {
        int o = g_off[i] + g_bsum[i >> 9];
        g_off[i] = o;
        g_cur[i] = o;
    }
}

__global__ void scatter2_kernel(const int* __restrict__ src,
                                const int* __restrict__ dst32,
                                const int* __restrict__ dst64, int e, int n) {
    int i = blockIdx.x * blockDim.x + threadIdx.x;
    int is64 = g_is64;
    if (i < e) {
        int d = is64 ? dst64[2 * i] : dst32[i];
        int s = is64 ? src[2 * i] : src[i];
        int p = atomicAdd(&g_cur[d], 1);
        g_srcs[p] = s;
        g_dsts[p] = d;
    } else if (i < e + n) {
        int v = i - e;
        int p = atomicAdd(&g_cur[v], 1);
        g_srcs[p] = v;
        g_dsts[p] = v;
    }
}

// ---------------- W transpose -> fp16 ----------------
__global__ void wsplit_kernel(const float* __restrict__ W,
                              __half* __restrict__ Bh, int K, int Nd) {
    int i = blockIdx.x * blockDim.x + threadIdx.x;
    if (i >= K * Nd) return;
    int k = i / Nd, nn = i % Nd;
    Bh[(size_t)nn * K + k] = __float2half_rn(W[i]);
}

// ---------------- edge weights ----------------
__global__ void edgew_kernel(int t) {
    int i = blockIdx.x * blockDim.x + threadIdx.x;
    if (i >= t) return;
    int s = g_srcs[i];
    int d = g_dsts[i];
    g_w[i] = __expf(leaky02(g_as[s] + g_ad[d]));
}

// ---------------- mma.sync fp16 GEMM + fused alpha dots ----------------
// A16=false: A fp32 (layer 1) via register prefetch + pack.
// A16=true:  A fp16 (g_x16) staged directly via cp.async 16B.
template <int NDIM, bool A16>
__global__ void __launch_bounds__(256, 2)
mma_gemm_kernel(const float* __restrict__ Af32, const __half* __restrict__ Ah16,
                int M, int K,
                const __half* __restrict__ Bhi,
                const float* __restrict__ a_src, const float* __restrict__ a_dst) {
    constexpr int ABYTES = 128 * 128;
    constexpr int BP = NDIM / 16;
    constexpr int MT = (NDIM == 128) ? 2 : 1;
    constexpr int MROWS = MT * 16;
    extern __shared__ char smraw[];
    char* smem = (char*)(((uintptr_t)smraw + 1023) & ~(uintptr_t)1023);
    uint32_t aHiB = smem_u32(smem);
    uint32_t bHiB = aHiB + ABYTES;

    const int tid = threadIdx.x, wid = tid >> 5, lane = tid & 31;
    const int rowBase = blockIdx.x * 128;
    const int wm = (NDIM == 128) ? (wid & 3) : wid;
    const int wn = (NDIM == 128) ? (wid >> 2) : 0;

    float acc[MT][8][4];
    #pragma unroll
    for (int mt = 0; mt < MT; mt++)
        #pragma unroll
        for (int nt = 0; nt < 8; nt++)
            #pragma unroll
            for (int q = 0; q < 4; q++) acc[mt][nt][q] = 0.f;

    const int aRow = wm * MROWS + (lane & 7) + ((lane >> 3) & 1) * 8;
    const uint32_t aRowOff = (uint32_t)aRow * 128;
    const uint32_t aSwz = (uint32_t)(lane & 7) << 4;
    const uint32_t aHalf = ((lane >> 4) & 1) * 16;
    const uint32_t bRow4 = (uint32_t)((lane & 7) | ((lane >> 4) << 3));
    const uint32_t bRowOff4 = (uint32_t)(wn * 64 + bRow4) * 128;
    const uint32_t bSwz4 = (uint32_t)(lane & 7) << 4;
    const uint32_t bHalf4 = ((lane >> 3) & 1) * 16;

    const int sr = tid >> 4;
    const int cg = (tid & 15) * 4;
    const uint32_t stCol = (uint32_t)(cg * 2);
    const int a16row = tid >> 3;        // 0..31
    const uint32_t a16seg = (uint32_t)(tid & 7) * 16;

    const int nChunks = K >> 6;

    float4 pref[8];
    if constexpr (!A16) {
        #pragma unroll
        for (int p = 0; p < 8; p++) {
            int gr = rowBase + p * 16 + sr;
            pref[p] = make_float4(0.f, 0.f, 0.f, 0.f);
            if (gr < M)
                pref[p] = *reinterpret_cast<const float4*>(&Af32[(size_t)gr * K + cg]);
        }
    }

    for (int c = 0; c < nChunks; c++) {
        const int k0 = c << 6;
        // ---- B staging via cp.async ----
        #pragma unroll
        for (int p = 0; p < BP; p++) {
            int r = p * 16 + sr;
            uint32_t off = (uint32_t)r * 128 + (stCol ^ ((uint32_t)(r & 7) << 4));
            cp_async8(bHiB + off, &Bhi[(size_t)r * K + k0 + cg]);
        }
        // ---- A staging ----
        if constexpr (A16) {
            #pragma unroll
            for (int p = 0; p < 4; p++) {
                int r = p * 32 + a16row;
                int gr = rowBase + r;
                const __half* src = (gr < M)
                    ? &Ah16[(size_t)gr * K + k0 + (tid & 7) * 8]
                    : Ah16;
                uint32_t off = (uint32_t)r * 128 + (a16seg ^ ((uint32_t)(r & 7) << 4));
                cp_async16(aHiB + off, src);
            }
        } else {
            #pragma unroll
            for (int p = 0; p < 8; p++) {
                int r = p * 16 + sr;
                float4 v = pref[p];
                uint32_t off = (uint32_t)r * 128 + (stCol ^ ((uint32_t)(r & 7) << 4));
                sts64(aHiB + off, pack_f16(v.x, v.y), pack_f16(v.z, v.w));
            }
        }
        cp_async_commit_wait();
        __syncthreads();

        // ---- prefetch fp32 A chunk c+1 (overlaps with MMA) ----
        if constexpr (!A16) {
            if (c + 1 < nChunks) {
                const int k1 = (c + 1) << 6;
                #pragma unroll
                for (int p = 0; p < 8; p++) {
                    int gr = rowBase + p * 16 + sr;
                    pref[p] = make_float4(0.f, 0.f, 0.f, 0.f);
                    if (gr < M)
                        pref[p] = *reinterpret_cast<const float4*>(&Af32[(size_t)gr * K + k1 + cg]);
                }
            }
        }

        // ---- compute: plain fp16 ----
        #pragma unroll
        for (int kt = 0; kt < 4; kt++) {
            uint32_t kc = (uint32_t)kt * 32;
            uint32_t aoff = aRowOff + ((kc + aHalf) ^ aSwz);
            uint32_t ahi[MT][4];
            #pragma unroll
            for (int mt = 0; mt < MT; mt++)
                ldm_x4(ahi[mt], aHiB + aoff + (uint32_t)mt * 2048);
            uint32_t bcol = (kc + bHalf4) ^ bSwz4;
            #pragma unroll
            for (int np = 0; np < 4; np++) {
                uint32_t boff = bRowOff4 + (uint32_t)np * 2048 + bcol;
                uint32_t bhi[4];
                ldm_x4(bhi, bHiB + boff);
                #pragma unroll
                for (int mt = 0; mt < MT; mt++) {
                    mma_f16(acc[mt][2 * np],     ahi[mt], &bhi[0]);
                    mma_f16(acc[mt][2 * np + 1], ahi[mt], &bhi[2]);
                }
            }
        }
        __syncthreads();
    }

    // ---- epilogue: write h (fp16) + alpha dot partials ----
    int r0 = rowBase + wm * MROWS + (lane >> 2);
    int colb = (lane & 3) * 2;
    float sp[MT][2], dp[MT][2];
    #pragma unroll
    for (int mt = 0; mt < MT; mt++) { sp[mt][0] = sp[mt][1] = dp[mt][0] = dp[mt][1] = 0.f; }

    #pragma unroll
    for (int mt = 0; mt < MT; mt++) {
        int rA = r0 + mt * 16;
        #pragma unroll
        for (int nt = 0; nt < 8; nt++) {
            int col = wn * 64 + nt * 8 + colb;
            float a0 = a_src[col], a1 = a_src[col + 1];
            float e0 = a_dst[col], e1 = a_dst[col + 1];
            sp[mt][0] = fmaf(acc[mt][nt][0], a0, fmaf(acc[mt][nt][1], a1, sp[mt][0]));
            dp[mt][0] = fmaf(acc[mt][nt][0], e0, fmaf(acc[mt][nt][1], e1, dp[mt][0]));
            sp[mt][1] = fmaf(acc[mt][nt][2], a0, fmaf(acc[mt][nt][3], a1, sp[mt][1]));
            dp[mt][1] = fmaf(acc[mt][nt][2], e0, fmaf(acc[mt][nt][3], e1, dp[mt][1]));
            if (rA < M)
                *reinterpret_cast<__half2*>(&g_h16[(size_t)rA * NDIM + col]) =
                    __floats2half2_rn(acc[mt][nt][0], acc[mt][nt][1]);
            if (rA + 8 < M)
                *reinterpret_cast<__half2*>(&g_h16[(size_t)(rA + 8) * NDIM + col]) =
                    __floats2half2_rn(acc[mt][nt][2], acc[mt][nt][3]);
        }
    }
    #pragma unroll
    for (int o = 1; o <= 2; o <<= 1) {
        #pragma unroll
        for (int mt = 0; mt < MT; mt++) {
            sp[mt][0] += __shfl_xor_sync(0xffffffffu, sp[mt][0], o);
            dp[mt][0] += __shfl_xor_sync(0xffffffffu, dp[mt][0], o);
            sp[mt][1] += __shfl_xor_sync(0xffffffffu, sp[mt][1], o);
            dp[mt][1] += __shfl_xor_sync(0xffffffffu, dp[mt][1], o);
        }
    }

    if constexpr (NDIM == 128) {
        float* sal = (float*)smem;   // reuse A region
        __syncthreads();
        if ((lane & 3) == 0) {
            int lr = wm * MROWS + (lane >> 2);
            #pragma unroll
            for (int mt = 0; mt < MT; mt++) {
                #pragma unroll
                for (int rh = 0; rh < 2; rh++) {
                    int row = lr + mt * 16 + rh * 8;
                    sal[row * 4 + wn * 2]     = (rh == 0) ? sp[mt][0] : sp[mt][1];
                    sal[row * 4 + wn * 2 + 1] = (rh == 0) ? dp[mt][0] : dp[mt][1];
                }
            }
        }
        __syncthreads();
        if (tid < 128) {
            int gr = rowBase + tid;
            if (gr < M) {
                g_as[gr] = sal[tid * 4] + sal[tid * 4 + 2];
                g_ad[gr] = sal[tid * 4 + 1] + sal[tid * 4 + 3];
            }
        }
    } else {
        if ((lane & 3) == 0) {
            if (r0 < M)     { g_as[r0] = sp[0][0];     g_ad[r0] = dp[0][0]; }
            if (r0 + 8 < M) { g_as[r0 + 8] = sp[0][1]; g_ad[r0 + 8] = dp[0][1]; }
        }
    }
}

// ---------------- aggregation with precomputed edge weights, fp16 h gather ----------------
template <int DO, bool TO_GX>
__global__ void aggregate_kernel(const float* __restrict__ bias,
                                 float* __restrict__ outp, int n) {
    constexpr int VEC = DO / 32;
    int node = (blockIdx.x * blockDim.x + threadIdx.x) >> 5;
    int lane = threadIdx.x & 31;
    if (node >= n) return;
    int s0 = g_off[node], s1 = g_off[node + 1];

    float acc[VEC];
    #pragma unroll
    for (int k = 0; k < VEC; k++) acc[k] = 0.f;
    float ssum = 0.f;

    const __half* hb = g_h16;
    int j = s0;
    #pragma unroll 1
    for (; j + 8 <= s1; j += 8) {
        int s[8];
        float w[8];
        #pragma unroll
        for (int q = 0; q < 8; q++) { s[q] = g_srcs[j + q]; w[q] = g_w[j + q]; }
        if constexpr (VEC == 4) {
            uint2 rr[8];
            #pragma unroll
            for (int q = 0; q < 8; q++)
                rr[q] = *reinterpret_cast<const uint2*>(&hb[(size_t)s[q] * DO + lane * 4]);
            #pragma unroll
            for (int q = 0; q < 8; q++) {
                ssum += w[q];
                float2 f0 = __half22float2(*reinterpret_cast<__half2*>(&rr[q].x));
                float2 f1 = __half22float2(*reinterpret_cast<__half2*>(&rr[q].y));
                acc[0] = fmaf(w[q], f0.x, acc[0]);
                acc[1] = fmaf(w[q], f0.y, acc[1]);
                acc[2] = fmaf(w[q], f1.x, acc[2]);
                acc[3] = fmaf(w[q], f1.y, acc[3]);
            }
        } else {
            uint32_t rr[8];
            #pragma unroll
            for (int q = 0; q < 8; q++)
                rr[q] = *reinterpret_cast<const uint32_t*>(&hb[(size_t)s[q] * DO + lane * 2]);
            #pragma unroll
            for (int q = 0; q < 8; q++) {
                ssum += w[q];
                float2 f0 = __half22float2(*reinterpret_cast<__half2*>(&rr[q]));
                acc[0] = fmaf(w[q], f0.x, acc[0]);
                acc[1] = fmaf(w[q], f0.y, acc[1]);
            }
        }
    }
    #pragma unroll 1
    for (; j < s1; ++j) {
        int s = g_srcs[j];
        float w = g_w[j];
        ssum += w;
        if constexpr (VEC == 4) {
            uint2 r = *reinterpret_cast<const uint2*>(&hb[(size_t)s * DO + lane * 4]);
            float2 f0 = __half22float2(*reinterpret_cast<__half2*>(&r.x));
            float2 f1 = __half22float2(*reinterpret_cast<__half2*>(&r.y));
            acc[0] = fmaf(w, f0.x, acc[0]);
            acc[1] = fmaf(w, f0.y, acc[1]);
            acc[2] = fmaf(w, f1.x, acc[2]);
            acc[3] = fmaf(w, f1.y, acc[3]);
        } else {
            uint32_t r = *reinterpret_cast<const uint32_t*>(&hb[(size_t)s * DO + lane * 2]);
            float2 f0 = __half22float2(*reinterpret_cast<__half2*>(&r));
            acc[0] = fmaf(w, f0.x, acc[0]);
            acc[1] = fmaf(w, f0.y, acc[1]);
        }
    }
    float inv = 1.f / ssum;
    #pragma unroll
    for (int k = 0; k < VEC; k++) {
        float o = fmaf(acc[k], inv, bias[lane * VEC + k]);
        acc[k] = o > 0.f ? o : 0.25f * o;
    }
    if constexpr (TO_GX) {
        __half* xp = &g_x16[(size_t)node * DO + lane * VEC];
        if constexpr (VEC == 4) {
            uint2 v;
            *reinterpret_cast<__half2*>(&v.x) = __floats2half2_rn(acc[0], acc[1]);
            *reinterpret_cast<__half2*>(&v.y) = __floats2half2_rn(acc[2], acc[3]);
            *reinterpret_cast<uint2*>(xp) = v;
        } else {
            *reinterpret_cast<__half2*>(xp) = __floats2half2_rn(acc[0], acc[1]);
        }
    } else {
        float* op = &outp[(size_t)node * DO + lane * VEC];
        if constexpr (VEC == 4)
            *reinterpret_cast<float4*>(op) = make_float4(acc[0], acc[1], acc[2], acc[3]);
        else
            *reinterpret_cast<float2*>(op) = make_float2(acc[0], acc[1]);
    }
}

// ---------------- launch ----------------
extern "C" void kernel_launch(void* const* d_in, const int* in_sizes, int n_in,
                              void* d_out, int out_size) {
    const float* data = (const float*)d_in[0];
    const int*   adj  = (const int*)d_in[1];
    const float* W1  = (const float*)d_in[2];
    const float* as1 = (const float*)d_in[3];
    const float* ad1 = (const float*)d_in[4];
    const float* b1  = (const float*)d_in[5];
    const float* W2  = (const float*)d_in[6];
    const float* as2 = (const float*)d_in[7];
    const float* ad2 = (const float*)d_in[8];
    const float* b2  = (const float*)d_in[9];
    const float* W3  = (const float*)d_in[10];
    const float* as3 = (const float*)d_in[11];
    const float* ad3 = (const float*)d_in[12];
    const float* b3  = (const float*)d_in[13];

    int Nn = in_sizes[0] / 512;
    int Ee = in_sizes[1] / 2;
    int Te = Ee + Nn;

    static cudaStream_t s2 = nullptr;
    static cudaEvent_t evFork = nullptr, evJoin = nullptr;
    static __half *pB1h, *pB2h, *pB3h, *pX16;
    if (s2 == nullptr) {
        cudaStreamCreateWithFlags(&s2, cudaStreamNonBlocking);
        cudaEventCreateWithFlags(&evFork, cudaEventDisableTiming);
        cudaEventCreateWithFlags(&evJoin, cudaEventDisableTiming);
        void* p;
        cudaGetSymbolAddress(&p, g_B1h); pB1h = (__half*)p;
        cudaGetSymbolAddress(&p, g_B2h); pB2h = (__half*)p;
        cudaGetSymbolAddress(&p, g_B3h); pB3h = (__half*)p;
        cudaGetSymbolAddress(&p, g_x16); pX16 = (__half*)p;
    }

    const int SM128 = 128 * 128 + 128 * 128 + 1024;  // 16K A + 16K B + pad
    const int SM64  = 128 * 128 + 64 * 128 + 1024;   // 16K A + 8K B + pad
    cudaFuncSetAttribute((const void*)mma_gemm_kernel<128, false>,
                         cudaFuncAttributeMaxDynamicSharedMemorySize, SM128);
    cudaFuncSetAttribute((const void*)mma_gemm_kernel<128, true>,
                         cudaFuncAttributeMaxDynamicSharedMemorySize, SM128);
    cudaFuncSetAttribute((const void*)mma_gemm_kernel<64, true>,
                         cudaFuncAttributeMaxDynamicSharedMemorySize, SM64);

    const int T = 256;
    int warpGrid = (Nn * 32 + T - 1) / T;
    int edgeGrid = (Te + T - 1) / T;
    const int* dst32 = adj + Ee;
    const int* dst64 = adj + 2 * (size_t)Ee;
    int gBlocks = (Nn + 127) / 128;
    int nb = (Nn + SCAN_BS - 1) / SCAN_BS;

    cudaEventRecord(evFork, 0);
    cudaStreamWaitEvent(s2, evFork, 0);
    detect_kernel<<<1, 32, 0, s2>>>(adj);
    init_deg_kernel<<<(Nn + T - 1) / T, T, 0, s2>>>(Nn);

    wsplit_kernel<<<(512 * 128 + T - 1) / T, T>>>(W1, pB1h, 512, 128);
    mma_gemm_kernel<128, false><<<gBlocks, 256, SM128>>>(
        data, nullptr, Nn, 512, pB1h, as1, ad1);

    count2_kernel<<<(Ee + T - 1) / T, T, 0, s2>>>(dst32, dst64, Ee);
    blockscan_kernel<<<nb, SCAN_BS, 0, s2>>>(Nn);
    bsumscan_kernel<<<1, 512, 0, s2>>>(nb, Nn);
    addoff_kernel<<<(Nn + T - 1) / T, T, 0, s2>>>(Nn);
    scatter2_kernel<<<(Ee + Nn + T - 1) / T, T, 0, s2>>>(adj, dst32, dst64, Ee, Nn);
    wsplit_kernel<<<(128 * 128 + T - 1) / T, T, 0, s2>>>(W2, pB2h, 128, 128);
    wsplit_kernel<<<(128 * 64 + T - 1) / T, T, 0, s2>>>(W3, pB3h, 128, 64);
    cudaEventRecord(evJoin, s2);

    cudaStreamWaitEvent(0, evJoin, 0);
    edgew_kernel<<<edgeGrid, T>>>(Te);
    aggregate_kernel<128, true><<<warpGrid, T>>>(b1, nullptr, Nn);

    mma_gemm_kernel<128, true><<<gBlocks, 256, SM128>>>(
        nullptr, pX16, Nn, 128, pB2h, as2, ad2);
    edgew_kernel<<<edgeGrid, T>>>(Te);
    aggregate_kernel<128, true><<<warpGrid, T>>>(b2, nullptr, Nn);

    mma_gemm_kernel<64, true><<<gBlocks, 256, SM64>>>(
        nullptr, pX16, Nn, 128, pB3h, as3, ad3);
    edgew_kernel<<<edgeGrid, T>>>(Te);
    aggregate_kernel<64, false><<<warpGrid, T>>>(b3, (float*)d_out, Nn);
}